// round 3
// baseline (speedup 1.0000x reference)
#include <cuda_runtime.h>
#include <cuda_bf16.h>
#include <math.h>

// Problem constants
#define BATCH   16384
#define IN_DIM  1280
#define BELLY   1024
#define SCALE_D 512
#define NBINS   100
#define NPAT    10

// Output layout (float32, concatenated flattened tuple)
#define Z_OFF   ((size_t)0)
#define TL_OFF  ((size_t)BATCH * SCALE_D)
#define PL_OFF  (TL_OFF + (size_t)BATCH * NBINS)
#define TC_OFF  (PL_OFF + (size_t)BATCH * NBINS * NPAT)
#define CV_OFF  (TC_OFF + (size_t)BATCH)

#define XMINF 1e-6f
#define XMAXF ((float)(1.0 - 1e-6))

// Scratch (device globals: allocation-guard safe)
__device__ float g_h[(size_t)BATCH * BELLY];      // 64 MB
__device__ float g_zraw[(size_t)BATCH * SCALE_D]; // 32 MB
__device__ int   g_maxclass;

// Exact timestep class. True value of t*100/1000 is t/10 (exact rational);
// truncation of the exact value for t >= 0 is integer floor division. The
// folded fp32 form t*fl(0.1f) provably rounds to the same integer for all
// t in [0, 1000). Pure integer math: no rounding ambiguity at all.
__device__ __forceinline__ int ts_class(int ts) {
    int c = ts / 10;
    return min(max(c, 0), NBINS - 1);
}

// ---------------------------------------------------------------------------
// Max timestep-class reduction
// ---------------------------------------------------------------------------
__global__ void k_maxclass(const int* __restrict__ ts, int n) {
    int i = blockIdx.x * blockDim.x + threadIdx.x;
    int local = 0;
    for (; i < n; i += gridDim.x * blockDim.x)
        local = max(local, ts_class(ts[i]));
#pragma unroll
    for (int o = 16; o; o >>= 1)
        local = max(local, __shfl_xor_sync(0xffffffffu, local, o));
    if ((threadIdx.x & 31) == 0) atomicMax(&g_maxclass, local);
}

// ---------------------------------------------------------------------------
// Tiled SGEMM: C[M,N] = op(A[M,K] @ B[K,N] + bias)
// BM=BN=128, BK=8, 256 threads, 8x8 per thread. M%128==0, K%8==0 assumed.
// ---------------------------------------------------------------------------
template<bool RELU, bool BIAS>
__global__ __launch_bounds__(256, 2)
void sgemm128(const float* __restrict__ A, const float* __restrict__ Bm,
              const float* __restrict__ bias, float* __restrict__ C,
              int M, int N, int K) {
    __shared__ float As[8][128];
    __shared__ float Bs[8][128];

    const int tid = threadIdx.x;
    const int bx = blockIdx.x;
    const int by = blockIdx.y;

    const int aRow = tid >> 1;
    const int aCol = (tid & 1) * 4;
    const float* Aptr = A + (size_t)(by * 128 + aRow) * K + aCol;

    const int bRow = tid >> 5;
    const int bCol = (tid & 31) * 4;
    const int bColG = bx * 128 + bCol;
    const bool bFull = (bColG + 3) < N;

    const int tx = tid & 15;
    const int ty = tid >> 4;

    float acc[8][8];
#pragma unroll
    for (int i = 0; i < 8; i++)
#pragma unroll
        for (int j = 0; j < 8; j++) acc[i][j] = 0.0f;

    for (int k0 = 0; k0 < K; k0 += 8) {
        float4 a4 = *(const float4*)(Aptr + k0);
        As[aCol + 0][aRow] = a4.x;
        As[aCol + 1][aRow] = a4.y;
        As[aCol + 2][aRow] = a4.z;
        As[aCol + 3][aRow] = a4.w;

        float4 b4;
        if (bFull) {
            b4 = *(const float4*)(Bm + (size_t)(k0 + bRow) * N + bColG);
        } else {
            const float* brow = Bm + (size_t)(k0 + bRow) * N;
            b4.x = (bColG + 0 < N) ? brow[bColG + 0] : 0.0f;
            b4.y = (bColG + 1 < N) ? brow[bColG + 1] : 0.0f;
            b4.z = (bColG + 2 < N) ? brow[bColG + 2] : 0.0f;
            b4.w = (bColG + 3 < N) ? brow[bColG + 3] : 0.0f;
        }
        *(float4*)&Bs[bRow][bCol] = b4;

        __syncthreads();

#pragma unroll
        for (int k = 0; k < 8; k++) {
            float4 a0 = *(const float4*)&As[k][ty * 8];
            float4 a1 = *(const float4*)&As[k][ty * 8 + 4];
            float4 b0 = *(const float4*)&Bs[k][tx * 8];
            float4 b1 = *(const float4*)&Bs[k][tx * 8 + 4];
            float ar[8] = {a0.x, a0.y, a0.z, a0.w, a1.x, a1.y, a1.z, a1.w};
            float br[8] = {b0.x, b0.y, b0.z, b0.w, b1.x, b1.y, b1.z, b1.w};
#pragma unroll
            for (int i = 0; i < 8; i++)
#pragma unroll
                for (int j = 0; j < 8; j++)
                    acc[i][j] = fmaf(ar[i], br[j], acc[i][j]);
        }
        __syncthreads();
    }

#pragma unroll
    for (int i = 0; i < 8; i++) {
        const size_t row = (size_t)(by * 128 + ty * 8 + i);
#pragma unroll
        for (int j = 0; j < 8; j++) {
            const int col = bx * 128 + tx * 8 + j;
            if (col < N) {
                float v = acc[i][j];
                if (BIAS) v += bias[col];
                if (RELU) v = fmaxf(v, 0.0f);
                C[row * N + col] = v;
            }
        }
    }
}

// ---------------------------------------------------------------------------
// Row normalize + cantor staircase. One block (128 threads) per row.
// ---------------------------------------------------------------------------
__global__ void k_norm_cantor(const float* __restrict__ zraw,
                              const float* __restrict__ w_pos,
                              const float* __restrict__ b_pos,
                              const float* __restrict__ alpha_p,
                              const int* __restrict__ timesteps,
                              float* __restrict__ out_z,
                              float* __restrict__ out_tc,
                              float* __restrict__ out_cv) {
    const int row = blockIdx.x;
    const int t = threadIdx.x;   // 0..127, 4 floats each (512 total)

    float4 zv = ((const float4*)(zraw + (size_t)row * SCALE_D))[t];

    float ss = zv.x * zv.x + zv.y * zv.y + zv.z * zv.z + zv.w * zv.w;
#pragma unroll
    for (int o = 16; o; o >>= 1)
        ss += __shfl_xor_sync(0xffffffffu, ss, o);
    __shared__ float s_ss[4];
    __shared__ double s_dd[4];
    const int wid = t >> 5, lid = t & 31;
    if (lid == 0) s_ss[wid] = ss;
    __syncthreads();
    const float tot_ss = s_ss[0] + s_ss[1] + s_ss[2] + s_ss[3];
    const float nrm = fmaxf(__fsqrt_rn(tot_ss), 1e-12f);

    // z = zraw / norm  (IEEE division, matching jnp elementwise divide)
    float4 o;
    o.x = __fdiv_rn(zv.x, nrm);
    o.y = __fdiv_rn(zv.y, nrm);
    o.z = __fdiv_rn(zv.z, nrm);
    o.w = __fdiv_rn(zv.w, nrm);
    ((float4*)(out_z + (size_t)row * SCALE_D))[t] = o;

    // dot(z, w_pos) in double for minimal perturbation into the chaotic map
    float4 wv = ((const float4*)w_pos)[t];
    double dd = (double)o.x * wv.x + (double)o.y * wv.y +
                (double)o.z * wv.z + (double)o.w * wv.w;
#pragma unroll
    for (int off = 16; off; off >>= 1)
        dd += __shfl_xor_sync(0xffffffffu, dd, off);
    if (lid == 0) s_dd[wid] = dd;
    __syncthreads();

    if (t == 0) {
        const float tot_dd = (float)(s_dd[0] + s_dd[1] + s_dd[2] + s_dd[3]);
        const int cls = ts_class(timesteps[row]);

        const int max_pos = g_maxclass + 1;
        const float denom = (float)max(max_pos - 1, 1);
        const float pos_f = (float)cls;
        float x = (max_pos > 1) ? __fdiv_rn(pos_f, denom) : pos_f;
        x = fminf(fmaxf(x, XMINF), XMAXF);

        const float pre = __fadd_rn(tot_dd, b_pos[0]);
        const float shift = __fmul_rn((float)tanh((double)pre), 0.3f);
        x = fminf(fmaxf(__fadd_rn(x, shift), XMINF), XMAXF);

        const double alpha = (double)(*alpha_p);
        const float tau_d = __fadd_rn(0.25f, 1e-8f);
        double Cx = 0.0;
        double w = 0.5;
#pragma unroll
        for (int L = 0; L < 12; L++) {
            const float y = __fmul_rn(x, 3.0f);
            const float d0 = __fadd_rn(y, -0.5f);
            const float d1 = __fadd_rn(y, -1.5f);
            const float d2 = __fadd_rn(y, -2.5f);
            const float l0 = __fdiv_rn(-__fmul_rn(d0, d0), tau_d);
            const float l1 = __fdiv_rn(-__fmul_rn(d1, d1), tau_d);
            const float l2 = __fdiv_rn(-__fmul_rn(d2, d2), tau_d);
            const float m = fmaxf(l0, fmaxf(l1, l2));
            const double e0 = exp((double)__fadd_rn(l0, -m));
            const double e1 = exp((double)__fadd_rn(l1, -m));
            const double e2 = exp((double)__fadd_rn(l2, -m));
            const double inv_s = 1.0 / (e0 + e1 + e2);
            const double bit = e1 * inv_s * alpha + e2 * inv_s;
            Cx += bit * w;
            w *= 0.5;
            x = __fadd_rn(y, -floorf(y));   // fp32 dynamics, matches ref recurrence
        }
        out_tc[row] = (float)cls;
        float cvf = (float)Cx;
        out_cv[row] = fminf(fmaxf(cvf, 0.0f), 1.0f);
    }
}

// ---------------------------------------------------------------------------
// Launch
// ---------------------------------------------------------------------------
extern "C" void kernel_launch(void* const* d_in, const int* in_sizes, int n_in,
                              void* d_out, int out_size) {
    const float* features = (const float*)d_in[0];
    const int*   timesteps = (const int*)d_in[1];
    const float* W1    = (const float*)d_in[2];
    const float* b1    = (const float*)d_in[3];
    const float* W2    = (const float*)d_in[4];
    const float* Wt    = (const float*)d_in[5];
    const float* bt    = (const float*)d_in[6];
    const float* Wp    = (const float*)d_in[7];
    const float* bp    = (const float*)d_in[8];
    const float* w_pos = (const float*)d_in[9];
    const float* b_pos = (const float*)d_in[10];
    const float* alpha = (const float*)d_in[11];

    float* out = (float*)d_out;
    float* out_z  = out + Z_OFF;
    float* out_tl = out + TL_OFF;
    float* out_pl = out + PL_OFF;
    float* out_tc = out + TC_OFF;
    float* out_cv = out + CV_OFF;

    float* h    = nullptr;
    float* zraw = nullptr;
    cudaGetSymbolAddress((void**)&h, g_h);
    cudaGetSymbolAddress((void**)&zraw, g_zraw);
    void* maxp = nullptr;
    cudaGetSymbolAddress(&maxp, g_maxclass);

    cudaMemsetAsync(maxp, 0, sizeof(int), 0);
    k_maxclass<<<32, 256>>>(timesteps, BATCH);

    {   // h = relu(features @ W1 + b1)
        dim3 grid((BELLY + 127) / 128, BATCH / 128);
        sgemm128<true, true><<<grid, 256>>>(features, W1, b1, h, BATCH, BELLY, IN_DIM);
    }
    {   // zraw = h @ W2
        dim3 grid((SCALE_D + 127) / 128, BATCH / 128);
        sgemm128<false, false><<<grid, 256>>>(h, W2, nullptr, zraw, BATCH, SCALE_D, BELLY);
    }
    k_norm_cantor<<<BATCH, 128>>>(zraw, w_pos, b_pos, alpha, timesteps,
                                  out_z, out_tc, out_cv);
    {   // timestep_logits = z @ Wt + bt
        dim3 grid((NBINS + 127) / 128, BATCH / 128);
        sgemm128<false, true><<<grid, 256>>>(out_z, Wt, bt, out_tl, BATCH, NBINS, SCALE_D);
    }
    {   // pattern_logits = z @ Wp + bp
        dim3 grid((NBINS * NPAT + 127) / 128, BATCH / 128);
        sgemm128<false, true><<<grid, 256>>>(out_z, Wp, bp, out_pl, BATCH, NBINS * NPAT, SCALE_D);
    }
}

// round 4
// speedup vs baseline: 1.3147x; 1.3147x over previous
#include <cuda_runtime.h>
#include <cuda_bf16.h>
#include <math.h>

// Problem constants
#define BATCH   16384
#define IN_DIM  1280
#define BELLY   1024
#define SCALE_D 512
#define NBINS   100
#define NPAT    10

// Output layout (float32, concatenated flattened tuple)
#define Z_OFF   ((size_t)0)
#define TL_OFF  ((size_t)BATCH * SCALE_D)
#define PL_OFF  (TL_OFF + (size_t)BATCH * NBINS)
#define TC_OFF  (PL_OFF + (size_t)BATCH * NBINS * NPAT)
#define CV_OFF  (TC_OFF + (size_t)BATCH)

#define XMINF 1e-6f
#define XMAXF ((float)(1.0 - 1e-6))

// Scratch (device globals: allocation-guard safe)
__device__ float  g_h[(size_t)BATCH * BELLY];      // 64 MB
__device__ float  g_zraw[(size_t)BATCH * SCALE_D]; // 32 MB
__device__ double g_dot[BATCH];                    // per-row z.w_pos
__device__ int    g_maxclass;

// Exact timestep class: truncation of exact t*100/1000 == t/10 integer division.
__device__ __forceinline__ int ts_class(int ts) {
    int c = ts / 10;
    return min(max(c, 0), NBINS - 1);
}

// ---------------------------------------------------------------------------
// Max timestep-class reduction
// ---------------------------------------------------------------------------
__global__ void k_maxclass(const int* __restrict__ ts, int n) {
    int i = blockIdx.x * blockDim.x + threadIdx.x;
    int local = 0;
    for (; i < n; i += gridDim.x * blockDim.x)
        local = max(local, ts_class(ts[i]));
#pragma unroll
    for (int o = 16; o; o >>= 1)
        local = max(local, __shfl_xor_sync(0xffffffffu, local, o));
    if ((threadIdx.x & 31) == 0) atomicMax(&g_maxclass, local);
}

// ---------------------------------------------------------------------------
// Tiled SGEMM: C[M,N] = op(A[M,K] @ B[K,N] + bias)
// BM=BN=128, BK=8, 256 threads, 8x8 per thread. M%128==0, K%8==0 assumed.
// ---------------------------------------------------------------------------
template<bool RELU, bool BIAS>
__global__ __launch_bounds__(256, 2)
void sgemm128(const float* __restrict__ A, const float* __restrict__ Bm,
              const float* __restrict__ bias, float* __restrict__ C,
              int M, int N, int K) {
    __shared__ float As[8][128];
    __shared__ float Bs[8][128];

    const int tid = threadIdx.x;
    const int bx = blockIdx.x;
    const int by = blockIdx.y;

    const int aRow = tid >> 1;
    const int aCol = (tid & 1) * 4;
    const float* Aptr = A + (size_t)(by * 128 + aRow) * K + aCol;

    const int bRow = tid >> 5;
    const int bCol = (tid & 31) * 4;
    const int bColG = bx * 128 + bCol;
    const bool bFull = (bColG + 3) < N;

    const int tx = tid & 15;
    const int ty = tid >> 4;

    float acc[8][8];
#pragma unroll
    for (int i = 0; i < 8; i++)
#pragma unroll
        for (int j = 0; j < 8; j++) acc[i][j] = 0.0f;

    for (int k0 = 0; k0 < K; k0 += 8) {
        float4 a4 = *(const float4*)(Aptr + k0);
        As[aCol + 0][aRow] = a4.x;
        As[aCol + 1][aRow] = a4.y;
        As[aCol + 2][aRow] = a4.z;
        As[aCol + 3][aRow] = a4.w;

        float4 b4;
        if (bFull) {
            b4 = *(const float4*)(Bm + (size_t)(k0 + bRow) * N + bColG);
        } else {
            const float* brow = Bm + (size_t)(k0 + bRow) * N;
            b4.x = (bColG + 0 < N) ? brow[bColG + 0] : 0.0f;
            b4.y = (bColG + 1 < N) ? brow[bColG + 1] : 0.0f;
            b4.z = (bColG + 2 < N) ? brow[bColG + 2] : 0.0f;
            b4.w = (bColG + 3 < N) ? brow[bColG + 3] : 0.0f;
        }
        *(float4*)&Bs[bRow][bCol] = b4;

        __syncthreads();

#pragma unroll
        for (int k = 0; k < 8; k++) {
            float4 a0 = *(const float4*)&As[k][ty * 8];
            float4 a1 = *(const float4*)&As[k][ty * 8 + 4];
            float4 b0 = *(const float4*)&Bs[k][tx * 8];
            float4 b1 = *(const float4*)&Bs[k][tx * 8 + 4];
            float ar[8] = {a0.x, a0.y, a0.z, a0.w, a1.x, a1.y, a1.z, a1.w};
            float br[8] = {b0.x, b0.y, b0.z, b0.w, b1.x, b1.y, b1.z, b1.w};
#pragma unroll
            for (int i = 0; i < 8; i++)
#pragma unroll
                for (int j = 0; j < 8; j++)
                    acc[i][j] = fmaf(ar[i], br[j], acc[i][j]);
        }
        __syncthreads();
    }

#pragma unroll
    for (int i = 0; i < 8; i++) {
        const size_t row = (size_t)(by * 128 + ty * 8 + i);
#pragma unroll
        for (int j = 0; j < 8; j++) {
            const int col = bx * 128 + tx * 8 + j;
            if (col < N) {
                float v = acc[i][j];
                if (BIAS) v += bias[col];
                if (RELU) v = fmaxf(v, 0.0f);
                C[row * N + col] = v;
            }
        }
    }
}

// ---------------------------------------------------------------------------
// Row normalize: one WARP per row, 8 rows per 256-thread block.
// Warp-shuffle reductions only. Writes z and the per-row dot to scratch.
// ---------------------------------------------------------------------------
__global__ __launch_bounds__(256)
void k_norm(const float* __restrict__ zraw,
            const float* __restrict__ w_pos,
            float* __restrict__ out_z,
            double* __restrict__ out_dot) {
    const int lid = threadIdx.x & 31;
    const int row = blockIdx.x * 8 + (threadIdx.x >> 5);

    // 512 floats per row = 128 float4 = 4 float4 per lane
    const float4* zr = (const float4*)(zraw + (size_t)row * SCALE_D);
    const float4* wp = (const float4*)w_pos;

    float4 zv[4];
    float ss = 0.0f;
#pragma unroll
    for (int i = 0; i < 4; i++) {
        zv[i] = zr[lid + 32 * i];
        ss += zv[i].x * zv[i].x + zv[i].y * zv[i].y +
              zv[i].z * zv[i].z + zv[i].w * zv[i].w;
    }
#pragma unroll
    for (int o = 16; o; o >>= 1)
        ss += __shfl_xor_sync(0xffffffffu, ss, o);

    const float nrm = fmaxf(__fsqrt_rn(ss), 1e-12f);

    float4* zo = (float4*)(out_z + (size_t)row * SCALE_D);
    double dd = 0.0;
#pragma unroll
    for (int i = 0; i < 4; i++) {
        float4 o, wv = wp[lid + 32 * i];
        o.x = __fdiv_rn(zv[i].x, nrm);
        o.y = __fdiv_rn(zv[i].y, nrm);
        o.z = __fdiv_rn(zv[i].z, nrm);
        o.w = __fdiv_rn(zv[i].w, nrm);
        zo[lid + 32 * i] = o;
        dd += (double)o.x * wv.x + (double)o.y * wv.y +
              (double)o.z * wv.z + (double)o.w * wv.w;
    }
#pragma unroll
    for (int o = 16; o; o >>= 1)
        dd += __shfl_xor_sync(0xffffffffu, dd, o);

    if (lid == 0) out_dot[row] = dd;
}

// ---------------------------------------------------------------------------
// Cantor staircase: one THREAD per row, fully parallel.
// Numerics identical to the passing R3 version.
// ---------------------------------------------------------------------------
__global__ __launch_bounds__(256)
void k_cantor(const double* __restrict__ dot,
              const float* __restrict__ b_pos,
              const float* __restrict__ alpha_p,
              const int* __restrict__ timesteps,
              float* __restrict__ out_tc,
              float* __restrict__ out_cv) {
    const int row = blockIdx.x * blockDim.x + threadIdx.x;
    if (row >= BATCH) return;

    const float tot_dd = (float)dot[row];
    const int cls = ts_class(timesteps[row]);

    const int max_pos = g_maxclass + 1;
    const float denom = (float)max(max_pos - 1, 1);
    const float pos_f = (float)cls;
    float x = (max_pos > 1) ? __fdiv_rn(pos_f, denom) : pos_f;
    x = fminf(fmaxf(x, XMINF), XMAXF);

    const float pre = __fadd_rn(tot_dd, b_pos[0]);
    const float shift = __fmul_rn((float)tanh((double)pre), 0.3f);
    x = fminf(fmaxf(__fadd_rn(x, shift), XMINF), XMAXF);

    const double alpha = (double)(*alpha_p);
    const float tau_d = __fadd_rn(0.25f, 1e-8f);
    double Cx = 0.0;
    double w = 0.5;
#pragma unroll
    for (int L = 0; L < 12; L++) {
        const float y = __fmul_rn(x, 3.0f);
        const float d0 = __fadd_rn(y, -0.5f);
        const float d1 = __fadd_rn(y, -1.5f);
        const float d2 = __fadd_rn(y, -2.5f);
        const float l0 = __fdiv_rn(-__fmul_rn(d0, d0), tau_d);
        const float l1 = __fdiv_rn(-__fmul_rn(d1, d1), tau_d);
        const float l2 = __fdiv_rn(-__fmul_rn(d2, d2), tau_d);
        const float m = fmaxf(l0, fmaxf(l1, l2));
        const double e0 = exp((double)__fadd_rn(l0, -m));
        const double e1 = exp((double)__fadd_rn(l1, -m));
        const double e2 = exp((double)__fadd_rn(l2, -m));
        const double inv_s = 1.0 / (e0 + e1 + e2);
        const double bit = e1 * inv_s * alpha + e2 * inv_s;
        Cx += bit * w;
        w *= 0.5;
        x = __fadd_rn(y, -floorf(y));   // fp32 dynamics, matches ref recurrence
    }
    out_tc[row] = (float)cls;
    float cvf = (float)Cx;
    out_cv[row] = fminf(fmaxf(cvf, 0.0f), 1.0f);
}

// ---------------------------------------------------------------------------
// Launch
// ---------------------------------------------------------------------------
extern "C" void kernel_launch(void* const* d_in, const int* in_sizes, int n_in,
                              void* d_out, int out_size) {
    const float* features = (const float*)d_in[0];
    const int*   timesteps = (const int*)d_in[1];
    const float* W1    = (const float*)d_in[2];
    const float* b1    = (const float*)d_in[3];
    const float* W2    = (const float*)d_in[4];
    const float* Wt    = (const float*)d_in[5];
    const float* bt    = (const float*)d_in[6];
    const float* Wp    = (const float*)d_in[7];
    const float* bp    = (const float*)d_in[8];
    const float* w_pos = (const float*)d_in[9];
    const float* b_pos = (const float*)d_in[10];
    const float* alpha = (const float*)d_in[11];

    float* out = (float*)d_out;
    float* out_z  = out + Z_OFF;
    float* out_tl = out + TL_OFF;
    float* out_pl = out + PL_OFF;
    float* out_tc = out + TC_OFF;
    float* out_cv = out + CV_OFF;

    float* h    = nullptr;
    float* zraw = nullptr;
    double* dot = nullptr;
    cudaGetSymbolAddress((void**)&h, g_h);
    cudaGetSymbolAddress((void**)&zraw, g_zraw);
    cudaGetSymbolAddress((void**)&dot, g_dot);
    void* maxp = nullptr;
    cudaGetSymbolAddress(&maxp, g_maxclass);

    cudaMemsetAsync(maxp, 0, sizeof(int), 0);
    k_maxclass<<<32, 256>>>(timesteps, BATCH);

    {   // h = relu(features @ W1 + b1)
        dim3 grid((BELLY + 127) / 128, BATCH / 128);
        sgemm128<true, true><<<grid, 256>>>(features, W1, b1, h, BATCH, BELLY, IN_DIM);
    }
    {   // zraw = h @ W2
        dim3 grid((SCALE_D + 127) / 128, BATCH / 128);
        sgemm128<false, false><<<grid, 256>>>(h, W2, nullptr, zraw, BATCH, SCALE_D, BELLY);
    }
    // normalize (warp/row) then cantor (thread/row)
    k_norm<<<BATCH / 8, 256>>>(zraw, w_pos, out_z, dot);
    k_cantor<<<(BATCH + 255) / 256, 256>>>(dot, b_pos, alpha, timesteps, out_tc, out_cv);

    {   // timestep_logits = z @ Wt + bt
        dim3 grid((NBINS + 127) / 128, BATCH / 128);
        sgemm128<false, true><<<grid, 256>>>(out_z, Wt, bt, out_tl, BATCH, NBINS, SCALE_D);
    }
    {   // pattern_logits = z @ Wp + bp
        dim3 grid((NBINS * NPAT + 127) / 128, BATCH / 128);
        sgemm128<false, true><<<grid, 256>>>(out_z, Wp, bp, out_pl, BATCH, NBINS * NPAT, SCALE_D);
    }
}

// round 6
// speedup vs baseline: 1.3160x; 1.0010x over previous
#include <cuda_runtime.h>
#include <cuda_bf16.h>
#include <math.h>
#include <stdint.h>

// Problem constants
#define BATCH   16384
#define IN_DIM  1280
#define BELLY   1024
#define SCALE_D 512
#define NBINS   100
#define NPAT    10

// Output layout (float32, concatenated flattened tuple)
#define Z_OFF   ((size_t)0)
#define TL_OFF  ((size_t)BATCH * SCALE_D)
#define PL_OFF  (TL_OFF + (size_t)BATCH * NBINS)
#define TC_OFF  (PL_OFF + (size_t)BATCH * NBINS * NPAT)
#define CV_OFF  (TC_OFF + (size_t)BATCH)

#define XMINF 1e-6f
#define XMAXF ((float)(1.0 - 1e-6))

// Scratch (device globals: allocation-guard safe)
__device__ __nv_bfloat16 g_hh[(size_t)BATCH * BELLY];
__device__ __nv_bfloat16 g_hl[(size_t)BATCH * BELLY];
__device__ float         g_zraw[(size_t)BATCH * SCALE_D];
__device__ __nv_bfloat16 g_zh[(size_t)BATCH * SCALE_D];
__device__ __nv_bfloat16 g_zl[(size_t)BATCH * SCALE_D];
__device__ double        g_dot[BATCH];
__device__ int           g_maxclass;

// ---------------------------------------------------------------------------
// Helpers
// ---------------------------------------------------------------------------
__device__ __forceinline__ void mma16816(float* d, const uint32_t* a, const uint32_t* b) {
    asm volatile(
        "mma.sync.aligned.m16n8k16.row.col.f32.bf16.bf16.f32 "
        "{%0,%1,%2,%3}, {%4,%5,%6,%7}, {%8,%9}, {%0,%1,%2,%3};"
        : "+f"(d[0]), "+f"(d[1]), "+f"(d[2]), "+f"(d[3])
        : "r"(a[0]), "r"(a[1]), "r"(a[2]), "r"(a[3]), "r"(b[0]), "r"(b[1]));
}

__device__ __forceinline__ void split2(float x, __nv_bfloat16& h, __nv_bfloat16& l) {
    h = __float2bfloat16(x);
    l = __float2bfloat16(x - __bfloat162float(h));
}

__device__ __forceinline__ uint64_t pack4bf(__nv_bfloat16 a, __nv_bfloat16 b,
                                            __nv_bfloat16 c, __nv_bfloat16 d) {
    union { __nv_bfloat16 h[4]; uint64_t u; } u;
    u.h[0] = a; u.h[1] = b; u.h[2] = c; u.h[3] = d;
    return u.u;
}
__device__ __forceinline__ uint32_t pack2bf(__nv_bfloat16 a, __nv_bfloat16 b) {
    union { __nv_bfloat16 h[2]; uint32_t u; } u;
    u.h[0] = a; u.h[1] = b;
    return u.u;
}

// smem layout: 4 bf16 planes, each [128 rows][72 cols] (padded stride)
#define SROW 72
#define PLANE_BYTES (128 * SROW * 2)   // 18432
#define OFF_AH 0
#define OFF_AL (PLANE_BYTES)
#define OFF_BH (2 * PLANE_BYTES)
#define OFF_BL (3 * PLANE_BYTES)
#define SM_TOTAL (4 * PLANE_BYTES)     // 73728

// ---------------------------------------------------------------------------
// bf16 split GEMM on HMMA (mma.sync m16n8k16): C[M,N] = op(A@B + bias)
// Tile 128x128, BK=64, 256 threads (8 warps = 4M x 2N), warp tile 32x64.
// A fp32 [M,K] (or pre-split bf16 planes), B fp32 [K,N]. M%128==0, K%64==0.
// ---------------------------------------------------------------------------
template<int KCHUNKS, bool PRESPLIT, bool BIAS, bool RELU, bool SPLIT_OUT>
__global__ __launch_bounds__(256)
void tc_gemm(const float* __restrict__ Afp,
             const __nv_bfloat16* __restrict__ Ahi,
             const __nv_bfloat16* __restrict__ Alo,
             const float* __restrict__ B,
             const float* __restrict__ bias,
             float* __restrict__ C,
             __nv_bfloat16* __restrict__ Chi,
             __nv_bfloat16* __restrict__ Clo,
             int N) {
    constexpr int K = KCHUNKS * 64;
    extern __shared__ char smem[];
    __nv_bfloat16* sAh = (__nv_bfloat16*)(smem + OFF_AH);
    __nv_bfloat16* sAl = (__nv_bfloat16*)(smem + OFF_AL);
    __nv_bfloat16* sBh = (__nv_bfloat16*)(smem + OFF_BH);
    __nv_bfloat16* sBl = (__nv_bfloat16*)(smem + OFF_BL);
    const uint32_t* Ah32 = (const uint32_t*)sAh;   // row stride 36 u32
    const uint32_t* Al32 = (const uint32_t*)sAl;
    const uint32_t* Bh32 = (const uint32_t*)sBh;
    const uint32_t* Bl32 = (const uint32_t*)sBl;

    const int tid = threadIdx.x, wid = tid >> 5, lid = tid & 31;
    const int gid = lid >> 2, tig = lid & 3;
    const int mw = (wid & 3) * 32;        // warp M offset in tile
    const int nw = (wid >> 2) * 64;       // warp N offset in tile
    const int m0 = blockIdx.y * 128, n0 = blockIdx.x * 128;

    float acc[2][8][4];
#pragma unroll
    for (int i = 0; i < 2; i++)
#pragma unroll
        for (int j = 0; j < 8; j++)
#pragma unroll
            for (int q = 0; q < 4; q++) acc[i][j][q] = 0.0f;

    for (int c = 0; c < KCHUNKS; c++) {
        const int k0 = c * 64;
        __syncthreads();   // protect previous iteration's smem reads

        // ---- A tile fill: [128 m][64 k] -> hi/lo planes
        if (PRESPLIT) {
#pragma unroll
            for (int i = 0; i < 8; i++) {
                const int idx = tid + i * 256;
                const int row = idx >> 4, kg = idx & 15;
                const size_t g = (size_t)(m0 + row) * K + k0 + kg * 4;
                *(uint64_t*)(sAh + row * SROW + kg * 4) = *(const uint64_t*)(Ahi + g);
                *(uint64_t*)(sAl + row * SROW + kg * 4) = *(const uint64_t*)(Alo + g);
            }
        } else {
#pragma unroll
            for (int i = 0; i < 8; i++) {
                const int idx = tid + i * 256;
                const int row = idx >> 4, kg = idx & 15;
                const float4 a = *(const float4*)(Afp + (size_t)(m0 + row) * K + k0 + kg * 4);
                __nv_bfloat16 h0, l0, h1, l1, h2, l2, h3, l3;
                split2(a.x, h0, l0); split2(a.y, h1, l1);
                split2(a.z, h2, l2); split2(a.w, h3, l3);
                *(uint64_t*)(sAh + row * SROW + kg * 4) = pack4bf(h0, h1, h2, h3);
                *(uint64_t*)(sAl + row * SROW + kg * 4) = pack4bf(l0, l1, l2, l3);
            }
        }

        // ---- B tile fill: gmem [K,N] -> smem [128 n][64 k] (transposed)
#pragma unroll
        for (int i = 0; i < 8; i++) {
            const int idx = tid + i * 256;
            const int kk = idx >> 5, ng = idx & 31;
            const int n = n0 + ng * 4;
            float4 v;
            if (n + 3 < N) {
                v = *(const float4*)(B + (size_t)(k0 + kk) * N + n);
            } else {
                const float* br = B + (size_t)(k0 + kk) * N;
                v.x = (n + 0 < N) ? br[n + 0] : 0.0f;
                v.y = (n + 1 < N) ? br[n + 1] : 0.0f;
                v.z = (n + 2 < N) ? br[n + 2] : 0.0f;
                v.w = (n + 3 < N) ? br[n + 3] : 0.0f;
            }
            const float vv[4] = {v.x, v.y, v.z, v.w};
#pragma unroll
            for (int j = 0; j < 4; j++) {
                __nv_bfloat16 h, l;
                split2(vv[j], h, l);
                sBh[(ng * 4 + j) * SROW + kk] = h;
                sBl[(ng * 4 + j) * SROW + kk] = l;
            }
        }

        __syncthreads();

        // ---- compute: 4 ksteps of 16
#pragma unroll
        for (int ks = 0; ks < 4; ks++) {
            const int kb = ks * 8;   // u32 column base (k/2)
            uint32_t ah[2][4], al[2][4], bh[8][2], bl[8][2];
#pragma unroll
            for (int mat = 0; mat < 2; mat++) {
                const int r = mw + mat * 16 + gid;
                ah[mat][0] = Ah32[r * 36 + kb + tig];
                ah[mat][1] = Ah32[(r + 8) * 36 + kb + tig];
                ah[mat][2] = Ah32[r * 36 + kb + 4 + tig];
                ah[mat][3] = Ah32[(r + 8) * 36 + kb + 4 + tig];
                al[mat][0] = Al32[r * 36 + kb + tig];
                al[mat][1] = Al32[(r + 8) * 36 + kb + tig];
                al[mat][2] = Al32[r * 36 + kb + 4 + tig];
                al[mat][3] = Al32[(r + 8) * 36 + kb + 4 + tig];
            }
#pragma unroll
            for (int nat = 0; nat < 8; nat++) {
                const int n = nw + nat * 8 + gid;
                bh[nat][0] = Bh32[n * 36 + kb + tig];
                bh[nat][1] = Bh32[n * 36 + kb + 4 + tig];
                bl[nat][0] = Bl32[n * 36 + kb + tig];
                bl[nat][1] = Bl32[n * 36 + kb + 4 + tig];
            }
#pragma unroll
            for (int mat = 0; mat < 2; mat++)
#pragma unroll
                for (int nat = 0; nat < 8; nat++) {
                    mma16816(acc[mat][nat], ah[mat], bh[nat]);
                    mma16816(acc[mat][nat], ah[mat], bl[nat]);
                    mma16816(acc[mat][nat], al[mat], bh[nat]);
                }
        }
    }

    // ---- epilogue
#pragma unroll
    for (int mat = 0; mat < 2; mat++) {
        const int r0 = m0 + mw + mat * 16 + gid;
#pragma unroll
        for (int nat = 0; nat < 8; nat++) {
            const int n = n0 + nw + nat * 8 + tig * 2;
            float c0 = acc[mat][nat][0], c1 = acc[mat][nat][1];
            float c2 = acc[mat][nat][2], c3 = acc[mat][nat][3];
            if (BIAS) {
                const float bv0 = (n < N) ? bias[n] : 0.0f;
                const float bv1 = (n + 1 < N) ? bias[n + 1] : 0.0f;
                c0 += bv0; c1 += bv1; c2 += bv0; c3 += bv1;
            }
            if (RELU) {
                c0 = fmaxf(c0, 0.0f); c1 = fmaxf(c1, 0.0f);
                c2 = fmaxf(c2, 0.0f); c3 = fmaxf(c3, 0.0f);
            }
            if (SPLIT_OUT) {
                __nv_bfloat16 h0, l0, h1, l1;
                if (n + 1 < N) {
                    split2(c0, h0, l0); split2(c1, h1, l1);
                    *(uint32_t*)(Chi + (size_t)r0 * N + n) = pack2bf(h0, h1);
                    *(uint32_t*)(Clo + (size_t)r0 * N + n) = pack2bf(l0, l1);
                    split2(c2, h0, l0); split2(c3, h1, l1);
                    *(uint32_t*)(Chi + (size_t)(r0 + 8) * N + n) = pack2bf(h0, h1);
                    *(uint32_t*)(Clo + (size_t)(r0 + 8) * N + n) = pack2bf(l0, l1);
                } else if (n < N) {
                    split2(c0, h0, l0);
                    Chi[(size_t)r0 * N + n] = h0; Clo[(size_t)r0 * N + n] = l0;
                    split2(c2, h0, l0);
                    Chi[(size_t)(r0 + 8) * N + n] = h0; Clo[(size_t)(r0 + 8) * N + n] = l0;
                }
            } else {
                if (n + 1 < N) {
                    *(float2*)(C + (size_t)r0 * N + n) = make_float2(c0, c1);
                    *(float2*)(C + (size_t)(r0 + 8) * N + n) = make_float2(c2, c3);
                } else if (n < N) {
                    C[(size_t)r0 * N + n] = c0;
                    C[(size_t)(r0 + 8) * N + n] = c2;
                }
            }
        }
    }
}

// Exact timestep class: truncation of exact t*100/1000 == t/10 integer division.
__device__ __forceinline__ int ts_class(int ts) {
    int c = ts / 10;
    return min(max(c, 0), NBINS - 1);
}

__global__ void k_maxclass(const int* __restrict__ ts, int n) {
    int i = blockIdx.x * blockDim.x + threadIdx.x;
    int local = 0;
    for (; i < n; i += gridDim.x * blockDim.x)
        local = max(local, ts_class(ts[i]));
#pragma unroll
    for (int o = 16; o; o >>= 1)
        local = max(local, __shfl_xor_sync(0xffffffffu, local, o));
    if ((threadIdx.x & 31) == 0) atomicMax(&g_maxclass, local);
}

// ---------------------------------------------------------------------------
// Row normalize: one WARP per row; writes z (fp32), z splits (bf16), and dot.
// ---------------------------------------------------------------------------
__global__ __launch_bounds__(256)
void k_norm(const float* __restrict__ zraw,
            const float* __restrict__ w_pos,
            float* __restrict__ out_z,
            __nv_bfloat16* __restrict__ zh,
            __nv_bfloat16* __restrict__ zl,
            double* __restrict__ out_dot) {
    const int lid = threadIdx.x & 31;
    const int row = blockIdx.x * 8 + (threadIdx.x >> 5);

    const float4* zr = (const float4*)(zraw + (size_t)row * SCALE_D);
    const float4* wp = (const float4*)w_pos;

    float4 zv[4];
    float ss = 0.0f;
#pragma unroll
    for (int i = 0; i < 4; i++) {
        zv[i] = zr[lid + 32 * i];
        ss += zv[i].x * zv[i].x + zv[i].y * zv[i].y +
              zv[i].z * zv[i].z + zv[i].w * zv[i].w;
    }
#pragma unroll
    for (int o = 16; o; o >>= 1)
        ss += __shfl_xor_sync(0xffffffffu, ss, o);

    const float nrm = fmaxf(__fsqrt_rn(ss), 1e-12f);

    float4* zo = (float4*)(out_z + (size_t)row * SCALE_D);
    double dd = 0.0;
#pragma unroll
    for (int i = 0; i < 4; i++) {
        float4 o;
        const float4 wv = wp[lid + 32 * i];
        o.x = __fdiv_rn(zv[i].x, nrm);
        o.y = __fdiv_rn(zv[i].y, nrm);
        o.z = __fdiv_rn(zv[i].z, nrm);
        o.w = __fdiv_rn(zv[i].w, nrm);
        zo[lid + 32 * i] = o;
        __nv_bfloat16 h0, l0, h1, l1, h2, l2, h3, l3;
        split2(o.x, h0, l0); split2(o.y, h1, l1);
        split2(o.z, h2, l2); split2(o.w, h3, l3);
        const size_t e = (size_t)row * SCALE_D + (lid + 32 * i) * 4;
        *(uint64_t*)(zh + e) = pack4bf(h0, h1, h2, h3);
        *(uint64_t*)(zl + e) = pack4bf(l0, l1, l2, l3);
        dd += (double)o.x * wv.x + (double)o.y * wv.y +
              (double)o.z * wv.z + (double)o.w * wv.w;
    }
#pragma unroll
    for (int o = 16; o; o >>= 1)
        dd += __shfl_xor_sync(0xffffffffu, dd, o);

    if (lid == 0) out_dot[row] = dd;
}

// ---------------------------------------------------------------------------
// Cantor staircase: one THREAD per row. Numerics identical to passing R4.
// ---------------------------------------------------------------------------
__global__ __launch_bounds__(256)
void k_cantor(const double* __restrict__ dot,
              const float* __restrict__ b_pos,
              const float* __restrict__ alpha_p,
              const int* __restrict__ timesteps,
              float* __restrict__ out_tc,
              float* __restrict__ out_cv) {
    const int row = blockIdx.x * blockDim.x + threadIdx.x;
    if (row >= BATCH) return;

    const float tot_dd = (float)dot[row];
    const int cls = ts_class(timesteps[row]);

    const int max_pos = g_maxclass + 1;
    const float denom = (float)max(max_pos - 1, 1);
    const float pos_f = (float)cls;
    float x = (max_pos > 1) ? __fdiv_rn(pos_f, denom) : pos_f;
    x = fminf(fmaxf(x, XMINF), XMAXF);

    const float pre = __fadd_rn(tot_dd, b_pos[0]);
    const float shift = __fmul_rn((float)tanh((double)pre), 0.3f);
    x = fminf(fmaxf(__fadd_rn(x, shift), XMINF), XMAXF);

    const double alpha = (double)(*alpha_p);
    const float tau_d = __fadd_rn(0.25f, 1e-8f);
    double Cx = 0.0;
    double w = 0.5;
#pragma unroll
    for (int L = 0; L < 12; L++) {
        const float y = __fmul_rn(x, 3.0f);
        const float d0 = __fadd_rn(y, -0.5f);
        const float d1 = __fadd_rn(y, -1.5f);
        const float d2 = __fadd_rn(y, -2.5f);
        const float l0 = __fdiv_rn(-__fmul_rn(d0, d0), tau_d);
        const float l1 = __fdiv_rn(-__fmul_rn(d1, d1), tau_d);
        const float l2 = __fdiv_rn(-__fmul_rn(d2, d2), tau_d);
        const float m = fmaxf(l0, fmaxf(l1, l2));
        const double e0 = exp((double)__fadd_rn(l0, -m));
        const double e1 = exp((double)__fadd_rn(l1, -m));
        const double e2 = exp((double)__fadd_rn(l2, -m));
        const double inv_s = 1.0 / (e0 + e1 + e2);
        const double bit = e1 * inv_s * alpha + e2 * inv_s;
        Cx += bit * w;
        w *= 0.5;
        x = __fadd_rn(y, -floorf(y));
    }
    out_tc[row] = (float)cls;
    float cvf = (float)Cx;
    out_cv[row] = fminf(fmaxf(cvf, 0.0f), 1.0f);
}

// ---------------------------------------------------------------------------
// Launch
// ---------------------------------------------------------------------------
extern "C" void kernel_launch(void* const* d_in, const int* in_sizes, int n_in,
                              void* d_out, int out_size) {
    const float* features = (const float*)d_in[0];
    const int*   timesteps = (const int*)d_in[1];
    const float* W1    = (const float*)d_in[2];
    const float* b1    = (const float*)d_in[3];
    const float* W2    = (const float*)d_in[4];
    const float* Wt    = (const float*)d_in[5];
    const float* bt    = (const float*)d_in[6];
    const float* Wp    = (const float*)d_in[7];
    const float* bp    = (const float*)d_in[8];
    const float* w_pos = (const float*)d_in[9];
    const float* b_pos = (const float*)d_in[10];
    const float* alpha = (const float*)d_in[11];

    float* out = (float*)d_out;
    float* out_z  = out + Z_OFF;
    float* out_tl = out + TL_OFF;
    float* out_pl = out + PL_OFF;
    float* out_tc = out + TC_OFF;
    float* out_cv = out + CV_OFF;

    __nv_bfloat16 *hh = nullptr, *hl = nullptr, *zh = nullptr, *zl = nullptr;
    float* zraw = nullptr;
    double* dot = nullptr;
    void* maxp = nullptr;
    cudaGetSymbolAddress((void**)&hh, g_hh);
    cudaGetSymbolAddress((void**)&hl, g_hl);
    cudaGetSymbolAddress((void**)&zraw, g_zraw);
    cudaGetSymbolAddress((void**)&zh, g_zh);
    cudaGetSymbolAddress((void**)&zl, g_zl);
    cudaGetSymbolAddress((void**)&dot, g_dot);
    cudaGetSymbolAddress(&maxp, g_maxclass);

    auto* g1  = tc_gemm<IN_DIM / 64, false, true, true, true>;
    auto* g2  = tc_gemm<BELLY / 64, true, false, false, false>;
    auto* g34 = tc_gemm<SCALE_D / 64, true, true, false, false>;

    cudaFuncSetAttribute(g1,  cudaFuncAttributeMaxDynamicSharedMemorySize, SM_TOTAL);
    cudaFuncSetAttribute(g2,  cudaFuncAttributeMaxDynamicSharedMemorySize, SM_TOTAL);
    cudaFuncSetAttribute(g34, cudaFuncAttributeMaxDynamicSharedMemorySize, SM_TOTAL);

    cudaMemsetAsync(maxp, 0, sizeof(int), 0);
    k_maxclass<<<32, 256>>>(timesteps, BATCH);

    // GEMM1: h(split) = relu(features @ W1 + b1)
    g1<<<dim3(BELLY / 128, BATCH / 128), 256, SM_TOTAL>>>(
        features, nullptr, nullptr, W1, b1, nullptr, hh, hl, BELLY);

    // GEMM2: zraw = h @ W2
    g2<<<dim3(SCALE_D / 128, BATCH / 128), 256, SM_TOTAL>>>(
        nullptr, hh, hl, W2, nullptr, zraw, nullptr, nullptr, SCALE_D);

    k_norm<<<BATCH / 8, 256>>>(zraw, w_pos, out_z, zh, zl, dot);
    k_cantor<<<(BATCH + 255) / 256, 256>>>(dot, b_pos, alpha, timesteps, out_tc, out_cv);

    // GEMM3: timestep_logits = z @ Wt + bt
    g34<<<dim3((NBINS + 127) / 128, BATCH / 128), 256, SM_TOTAL>>>(
        nullptr, zh, zl, Wt, bt, out_tl, nullptr, nullptr, NBINS);

    // GEMM4: pattern_logits = z @ Wp + bp
    g34<<<dim3((NBINS * NPAT + 127) / 128, BATCH / 128), 256, SM_TOTAL>>>(
        nullptr, zh, zl, Wp, bp, out_pl, nullptr, nullptr, NBINS * NPAT);
}

// round 7
// speedup vs baseline: 3.1425x; 2.3879x over previous
#include <cuda_runtime.h>
#include <cuda_bf16.h>
#include <math.h>
#include <stdint.h>

// Problem constants
#define BATCH   16384
#define IN_DIM  1280
#define BELLY   1024
#define SCALE_D 512
#define NBINS   100
#define NPAT    10

// Output layout (float32, concatenated flattened tuple)
#define Z_OFF   ((size_t)0)
#define TL_OFF  ((size_t)BATCH * SCALE_D)
#define PL_OFF  (TL_OFF + (size_t)BATCH * NBINS)
#define TC_OFF  (PL_OFF + (size_t)BATCH * NBINS * NPAT)
#define CV_OFF  (TC_OFF + (size_t)BATCH)

#define XMINF 1e-6f
#define XMAXF ((float)(1.0 - 1e-6))

// ---------------------------------------------------------------------------
// Scratch (device globals: allocation-guard safe)
// ---------------------------------------------------------------------------
__device__ __nv_bfloat16 g_fh[(size_t)BATCH * IN_DIM];
__device__ __nv_bfloat16 g_fl[(size_t)BATCH * IN_DIM];
__device__ __nv_bfloat16 g_hh[(size_t)BATCH * BELLY];
__device__ __nv_bfloat16 g_hl[(size_t)BATCH * BELLY];
__device__ __nv_bfloat16 g_zh[(size_t)BATCH * SCALE_D];
__device__ __nv_bfloat16 g_zl[(size_t)BATCH * SCALE_D];
__device__ float         g_zraw[(size_t)BATCH * SCALE_D];
// k-pair-packed weight planes: u32[K/2][Npad]
__device__ uint32_t g_w1h[(IN_DIM / 2) * 1024];
__device__ uint32_t g_w1l[(IN_DIM / 2) * 1024];
__device__ uint32_t g_w2h[(BELLY / 2) * 512];
__device__ uint32_t g_w2l[(BELLY / 2) * 512];
__device__ uint32_t g_wth[(SCALE_D / 2) * 128];
__device__ uint32_t g_wtl[(SCALE_D / 2) * 128];
__device__ uint32_t g_wph[(SCALE_D / 2) * 1024];
__device__ uint32_t g_wpl[(SCALE_D / 2) * 1024];
__device__ double g_dot[BATCH];
__device__ int    g_maxclass;

// ---------------------------------------------------------------------------
// Helpers
// ---------------------------------------------------------------------------
__device__ __forceinline__ void mma16816(float* d, const uint32_t* a, const uint32_t* b) {
    asm volatile(
        "mma.sync.aligned.m16n8k16.row.col.f32.bf16.bf16.f32 "
        "{%0,%1,%2,%3}, {%4,%5,%6,%7}, {%8,%9}, {%0,%1,%2,%3};"
        : "+f"(d[0]), "+f"(d[1]), "+f"(d[2]), "+f"(d[3])
        : "r"(a[0]), "r"(a[1]), "r"(a[2]), "r"(a[3]), "r"(b[0]), "r"(b[1]));
}
__device__ __forceinline__ void split2(float x, __nv_bfloat16& h, __nv_bfloat16& l) {
    h = __float2bfloat16(x);
    l = __float2bfloat16(x - __bfloat162float(h));
}
__device__ __forceinline__ uint64_t pack4bf(__nv_bfloat16 a, __nv_bfloat16 b,
                                            __nv_bfloat16 c, __nv_bfloat16 d) {
    union { __nv_bfloat16 h[4]; uint64_t u; } u;
    u.h[0] = a; u.h[1] = b; u.h[2] = c; u.h[3] = d;
    return u.u;
}
__device__ __forceinline__ uint32_t pack2bf(__nv_bfloat16 a, __nv_bfloat16 b) {
    union { __nv_bfloat16 h[2]; uint32_t u; } u;
    u.h[0] = a; u.h[1] = b;
    return u.u;
}
__device__ __forceinline__ uint32_t smem_u32(const void* p) {
    uint32_t a;
    asm("{ .reg .u64 t; cvta.to.shared.u64 t, %1; cvt.u32.u64 %0, t; }"
        : "=r"(a) : "l"(p));
    return a;
}
__device__ __forceinline__ void cp16(uint32_t dst, const void* src) {
    asm volatile("cp.async.cg.shared.global [%0], [%1], 16;"
                 :: "r"(dst), "l"(src));
}
#define CP_COMMIT() asm volatile("cp.async.commit_group;" ::: "memory")
#define CP_WAIT1()  asm volatile("cp.async.wait_group 1;" ::: "memory")
#define CP_WAIT0()  asm volatile("cp.async.wait_group 0;" ::: "memory")

// smem layout (per buffer): Ahi [128][72 bf16] 18432 B, Alo 18432 B,
//                           Bhi u32[32][136] 17408 B, Blo 17408 B
#define SA_STRIDE_B 144          // bytes per A row (72 bf16)
#define SB_STRIDE_B 544          // bytes per B k-pair row (136 u32)
#define OFF_AL 18432
#define OFF_BH 36864
#define OFF_BL 54272
#define BUF_BYTES 71680
#define SM_TOTAL (2 * BUF_BYTES)  // 143360

// ---------------------------------------------------------------------------
// bf16 split GEMM on HMMA: C[M,Npad] = op(A@B + bias)
// A: pre-split bf16 planes [M][K]. B: pre-packed u32 planes [K/2][Npad].
// Tile 128x128, BK=64, 256 threads (8 warps = 4M x 2N), cp.async + dbl buffer.
// ---------------------------------------------------------------------------
template<int KCHUNKS, bool BIAS, bool RELU, bool SPLIT_OUT>
__global__ __launch_bounds__(256)
void tc_gemm(const __nv_bfloat16* __restrict__ Ahi,
             const __nv_bfloat16* __restrict__ Alo,
             const uint32_t* __restrict__ Bh,
             const uint32_t* __restrict__ Bl,
             const float* __restrict__ bias,
             float* __restrict__ C,
             __nv_bfloat16* __restrict__ Chi,
             __nv_bfloat16* __restrict__ Clo,
             int N, int Npad) {
    constexpr int K = KCHUNKS * 64;
    extern __shared__ char smem[];
    const uint32_t sb = smem_u32(smem);

    const int tid = threadIdx.x, wid = tid >> 5, lid = tid & 31;
    const int gid = lid >> 2, tig = lid & 3;
    const int mw = (wid & 3) * 32;
    const int nw = (wid >> 2) * 64;
    const int m0 = blockIdx.y * 128, n0 = blockIdx.x * 128;

    float acc[2][8][4];
#pragma unroll
    for (int i = 0; i < 2; i++)
#pragma unroll
        for (int j = 0; j < 8; j++)
#pragma unroll
            for (int q = 0; q < 4; q++) acc[i][j][q] = 0.0f;

    // ---- async fill of one chunk into buffer boff
    auto fill = [&](int c, uint32_t boff) {
        const int k0 = c * 64;
        // A planes: 1024 16B-ops per plane / 256 threads = 4 iters
#pragma unroll
        for (int i = 0; i < 4; i++) {
            const int idx = tid + i * 256;
            const int row = idx >> 3, c8 = idx & 7;
            const uint32_t d = sb + boff + row * SA_STRIDE_B + c8 * 16;
            const size_t g = (size_t)(m0 + row) * K + k0 + c8 * 8;
            cp16(d, Ahi + g);
            cp16(d + OFF_AL, Alo + g);
        }
        // B planes: 1024 16B-ops per plane / 256 threads = 4 iters
#pragma unroll
        for (int i = 0; i < 4; i++) {
            const int idx = tid + i * 256;
            const int kp = idx >> 5, c16 = idx & 31;
            const uint32_t d = sb + boff + OFF_BH + kp * SB_STRIDE_B + c16 * 16;
            const size_t g = (size_t)((k0 >> 1) + kp) * Npad + n0 + c16 * 4;
            cp16(d, Bh + g);
            cp16(d + (OFF_BL - OFF_BH), Bl + g);
        }
    };

    fill(0, 0);
    CP_COMMIT();

    for (int c = 0; c < KCHUNKS; c++) {
        if (c + 1 < KCHUNKS) {
            fill(c + 1, (uint32_t)((c + 1) & 1) * BUF_BYTES);
            CP_COMMIT();
            CP_WAIT1();
        } else {
            CP_WAIT0();
        }
        __syncthreads();

        const uint32_t boff = (uint32_t)(c & 1) * BUF_BYTES;
        const uint32_t* A_h = (const uint32_t*)(smem + boff);            // [128][36]
        const uint32_t* A_l = (const uint32_t*)(smem + boff + OFF_AL);
        const uint32_t* B_h = (const uint32_t*)(smem + boff + OFF_BH);   // [32][136]
        const uint32_t* B_l = (const uint32_t*)(smem + boff + OFF_BL);

#pragma unroll
        for (int ks = 0; ks < 4; ks++) {
            const int kb = ks * 8;   // u32 (k-pair) base within chunk
            uint32_t ah[2][4], al[2][4], bh[8][2], bl[8][2];
#pragma unroll
            for (int mat = 0; mat < 2; mat++) {
                const int r = mw + mat * 16 + gid;
                ah[mat][0] = A_h[r * 36 + kb + tig];
                ah[mat][1] = A_h[(r + 8) * 36 + kb + tig];
                ah[mat][2] = A_h[r * 36 + kb + 4 + tig];
                ah[mat][3] = A_h[(r + 8) * 36 + kb + 4 + tig];
                al[mat][0] = A_l[r * 36 + kb + tig];
                al[mat][1] = A_l[(r + 8) * 36 + kb + tig];
                al[mat][2] = A_l[r * 36 + kb + 4 + tig];
                al[mat][3] = A_l[(r + 8) * 36 + kb + 4 + tig];
            }
#pragma unroll
            for (int nat = 0; nat < 8; nat++) {
                const int n = nw + nat * 8 + gid;
                bh[nat][0] = B_h[(kb + tig) * 136 + n];
                bh[nat][1] = B_h[(kb + 4 + tig) * 136 + n];
                bl[nat][0] = B_l[(kb + tig) * 136 + n];
                bl[nat][1] = B_l[(kb + 4 + tig) * 136 + n];
            }
#pragma unroll
            for (int mat = 0; mat < 2; mat++)
#pragma unroll
                for (int nat = 0; nat < 8; nat++) {
                    mma16816(acc[mat][nat], ah[mat], bh[nat]);
                    mma16816(acc[mat][nat], ah[mat], bl[nat]);
                    mma16816(acc[mat][nat], al[mat], bh[nat]);
                }
        }
        __syncthreads();   // all reads done before this buffer is refilled
    }

    // ---- epilogue
#pragma unroll
    for (int mat = 0; mat < 2; mat++) {
        const int r0 = m0 + mw + mat * 16 + gid;
#pragma unroll
        for (int nat = 0; nat < 8; nat++) {
            const int n = n0 + nw + nat * 8 + tig * 2;
            float c0 = acc[mat][nat][0], c1 = acc[mat][nat][1];
            float c2 = acc[mat][nat][2], c3 = acc[mat][nat][3];
            if (BIAS) {
                const float bv0 = (n < N) ? bias[n] : 0.0f;
                const float bv1 = (n + 1 < N) ? bias[n + 1] : 0.0f;
                c0 += bv0; c1 += bv1; c2 += bv0; c3 += bv1;
            }
            if (RELU) {
                c0 = fmaxf(c0, 0.0f); c1 = fmaxf(c1, 0.0f);
                c2 = fmaxf(c2, 0.0f); c3 = fmaxf(c3, 0.0f);
            }
            if (SPLIT_OUT) {
                __nv_bfloat16 h0, l0, h1, l1;
                if (n + 1 < N) {
                    split2(c0, h0, l0); split2(c1, h1, l1);
                    *(uint32_t*)(Chi + (size_t)r0 * N + n) = pack2bf(h0, h1);
                    *(uint32_t*)(Clo + (size_t)r0 * N + n) = pack2bf(l0, l1);
                    split2(c2, h0, l0); split2(c3, h1, l1);
                    *(uint32_t*)(Chi + (size_t)(r0 + 8) * N + n) = pack2bf(h0, h1);
                    *(uint32_t*)(Clo + (size_t)(r0 + 8) * N + n) = pack2bf(l0, l1);
                } else if (n < N) {
                    split2(c0, h0, l0);
                    Chi[(size_t)r0 * N + n] = h0; Clo[(size_t)r0 * N + n] = l0;
                    split2(c2, h0, l0);
                    Chi[(size_t)(r0 + 8) * N + n] = h0; Clo[(size_t)(r0 + 8) * N + n] = l0;
                }
            } else {
                if (n + 1 < N) {
                    *(float2*)(C + (size_t)r0 * N + n) = make_float2(c0, c1);
                    *(float2*)(C + (size_t)(r0 + 8) * N + n) = make_float2(c2, c3);
                } else if (n < N) {
                    C[(size_t)r0 * N + n] = c0;
                    C[(size_t)(r0 + 8) * N + n] = c2;
                }
            }
        }
    }
}

// ---------------------------------------------------------------------------
// Prep kernels
// ---------------------------------------------------------------------------
__global__ void k_split(const float* __restrict__ x, __nv_bfloat16* __restrict__ xh,
                        __nv_bfloat16* __restrict__ xl, int n4) {
    const int i = blockIdx.x * blockDim.x + threadIdx.x;
    if (i >= n4) return;
    const float4 v = ((const float4*)x)[i];
    __nv_bfloat16 h0, l0, h1, l1, h2, l2, h3, l3;
    split2(v.x, h0, l0); split2(v.y, h1, l1);
    split2(v.z, h2, l2); split2(v.w, h3, l3);
    ((uint64_t*)xh)[i] = pack4bf(h0, h1, h2, h3);
    ((uint64_t*)xl)[i] = pack4bf(l0, l1, l2, l3);
}

// W [K][N] fp32 -> k-pair packed u32 [K/2][Npad] hi/lo, zero padded
__global__ void k_pack(const float* __restrict__ W, uint32_t* __restrict__ Wh,
                       uint32_t* __restrict__ Wl, int N, int Npad, int total) {
    const int idx = blockIdx.x * blockDim.x + threadIdx.x;
    if (idx >= total) return;
    const int kp = idx / Npad, n = idx - kp * Npad;
    float v0 = 0.0f, v1 = 0.0f;
    if (n < N) {
        v0 = W[(size_t)(2 * kp) * N + n];
        v1 = W[(size_t)(2 * kp + 1) * N + n];
    }
    __nv_bfloat16 h0, l0, h1, l1;
    split2(v0, h0, l0); split2(v1, h1, l1);
    Wh[idx] = pack2bf(h0, h1);
    Wl[idx] = pack2bf(l0, l1);
}

// ---------------------------------------------------------------------------
// Exact timestep class + max reduction
// ---------------------------------------------------------------------------
__device__ __forceinline__ int ts_class(int ts) {
    int c = ts / 10;
    return min(max(c, 0), NBINS - 1);
}
__global__ void k_maxclass(const int* __restrict__ ts, int n) {
    int i = blockIdx.x * blockDim.x + threadIdx.x;
    int local = 0;
    for (; i < n; i += gridDim.x * blockDim.x)
        local = max(local, ts_class(ts[i]));
#pragma unroll
    for (int o = 16; o; o >>= 1)
        local = max(local, __shfl_xor_sync(0xffffffffu, local, o));
    if ((threadIdx.x & 31) == 0) atomicMax(&g_maxclass, local);
}

// ---------------------------------------------------------------------------
// Row normalize: one WARP per row; writes z (fp32), z splits (bf16), and dot.
// ---------------------------------------------------------------------------
__global__ __launch_bounds__(256)
void k_norm(const float* __restrict__ zraw,
            const float* __restrict__ w_pos,
            float* __restrict__ out_z,
            __nv_bfloat16* __restrict__ zh,
            __nv_bfloat16* __restrict__ zl,
            double* __restrict__ out_dot) {
    const int lid = threadIdx.x & 31;
    const int row = blockIdx.x * 8 + (threadIdx.x >> 5);

    const float4* zr = (const float4*)(zraw + (size_t)row * SCALE_D);
    const float4* wp = (const float4*)w_pos;

    float4 zv[4];
    float ss = 0.0f;
#pragma unroll
    for (int i = 0; i < 4; i++) {
        zv[i] = zr[lid + 32 * i];
        ss += zv[i].x * zv[i].x + zv[i].y * zv[i].y +
              zv[i].z * zv[i].z + zv[i].w * zv[i].w;
    }
#pragma unroll
    for (int o = 16; o; o >>= 1)
        ss += __shfl_xor_sync(0xffffffffu, ss, o);

    const float nrm = fmaxf(__fsqrt_rn(ss), 1e-12f);

    float4* zo = (float4*)(out_z + (size_t)row * SCALE_D);
    double dd = 0.0;
#pragma unroll
    for (int i = 0; i < 4; i++) {
        float4 o;
        const float4 wv = wp[lid + 32 * i];
        o.x = __fdiv_rn(zv[i].x, nrm);
        o.y = __fdiv_rn(zv[i].y, nrm);
        o.z = __fdiv_rn(zv[i].z, nrm);
        o.w = __fdiv_rn(zv[i].w, nrm);
        zo[lid + 32 * i] = o;
        __nv_bfloat16 h0, l0, h1, l1, h2, l2, h3, l3;
        split2(o.x, h0, l0); split2(o.y, h1, l1);
        split2(o.z, h2, l2); split2(o.w, h3, l3);
        const size_t e = (size_t)row * SCALE_D + (lid + 32 * i) * 4;
        *(uint64_t*)(zh + e) = pack4bf(h0, h1, h2, h3);
        *(uint64_t*)(zl + e) = pack4bf(l0, l1, l2, l3);
        dd += (double)o.x * wv.x + (double)o.y * wv.y +
              (double)o.z * wv.z + (double)o.w * wv.w;
    }
#pragma unroll
    for (int o = 16; o; o >>= 1)
        dd += __shfl_xor_sync(0xffffffffu, dd, o);

    if (lid == 0) out_dot[row] = dd;
}

// ---------------------------------------------------------------------------
// Cantor staircase: one THREAD per row. Numerics identical to passing R4/R6.
// ---------------------------------------------------------------------------
__global__ __launch_bounds__(256)
void k_cantor(const double* __restrict__ dot,
              const float* __restrict__ b_pos,
              const float* __restrict__ alpha_p,
              const int* __restrict__ timesteps,
              float* __restrict__ out_tc,
              float* __restrict__ out_cv) {
    const int row = blockIdx.x * blockDim.x + threadIdx.x;
    if (row >= BATCH) return;

    const float tot_dd = (float)dot[row];
    const int cls = ts_class(timesteps[row]);

    const int max_pos = g_maxclass + 1;
    const float denom = (float)max(max_pos - 1, 1);
    const float pos_f = (float)cls;
    float x = (max_pos > 1) ? __fdiv_rn(pos_f, denom) : pos_f;
    x = fminf(fmaxf(x, XMINF), XMAXF);

    const float pre = __fadd_rn(tot_dd, b_pos[0]);
    const float shift = __fmul_rn((float)tanh((double)pre), 0.3f);
    x = fminf(fmaxf(__fadd_rn(x, shift), XMINF), XMAXF);

    const double alpha = (double)(*alpha_p);
    const float tau_d = __fadd_rn(0.25f, 1e-8f);
    double Cx = 0.0;
    double w = 0.5;
#pragma unroll
    for (int L = 0; L < 12; L++) {
        const float y = __fmul_rn(x, 3.0f);
        const float d0 = __fadd_rn(y, -0.5f);
        const float d1 = __fadd_rn(y, -1.5f);
        const float d2 = __fadd_rn(y, -2.5f);
        const float l0 = __fdiv_rn(-__fmul_rn(d0, d0), tau_d);
        const float l1 = __fdiv_rn(-__fmul_rn(d1, d1), tau_d);
        const float l2 = __fdiv_rn(-__fmul_rn(d2, d2), tau_d);
        const float m = fmaxf(l0, fmaxf(l1, l2));
        const double e0 = exp((double)__fadd_rn(l0, -m));
        const double e1 = exp((double)__fadd_rn(l1, -m));
        const double e2 = exp((double)__fadd_rn(l2, -m));
        const double inv_s = 1.0 / (e0 + e1 + e2);
        const double bit = e1 * inv_s * alpha + e2 * inv_s;
        Cx += bit * w;
        w *= 0.5;
        x = __fadd_rn(y, -floorf(y));
    }
    out_tc[row] = (float)cls;
    float cvf = (float)Cx;
    out_cv[row] = fminf(fmaxf(cvf, 0.0f), 1.0f);
}

// ---------------------------------------------------------------------------
// Launch
// ---------------------------------------------------------------------------
extern "C" void kernel_launch(void* const* d_in, const int* in_sizes, int n_in,
                              void* d_out, int out_size) {
    const float* features = (const float*)d_in[0];
    const int*   timesteps = (const int*)d_in[1];
    const float* W1    = (const float*)d_in[2];
    const float* b1    = (const float*)d_in[3];
    const float* W2    = (const float*)d_in[4];
    const float* Wt    = (const float*)d_in[5];
    const float* bt    = (const float*)d_in[6];
    const float* Wp    = (const float*)d_in[7];
    const float* bp    = (const float*)d_in[8];
    const float* w_pos = (const float*)d_in[9];
    const float* b_pos = (const float*)d_in[10];
    const float* alpha = (const float*)d_in[11];

    float* out = (float*)d_out;
    float* out_z  = out + Z_OFF;
    float* out_tl = out + TL_OFF;
    float* out_pl = out + PL_OFF;
    float* out_tc = out + TC_OFF;
    float* out_cv = out + CV_OFF;

    __nv_bfloat16 *fh, *fl, *hh, *hl, *zh, *zl;
    uint32_t *w1h, *w1l, *w2h, *w2l, *wth, *wtl, *wph, *wpl;
    float* zraw; double* dot; void* maxp;
    cudaGetSymbolAddress((void**)&fh, g_fh);   cudaGetSymbolAddress((void**)&fl, g_fl);
    cudaGetSymbolAddress((void**)&hh, g_hh);   cudaGetSymbolAddress((void**)&hl, g_hl);
    cudaGetSymbolAddress((void**)&zh, g_zh);   cudaGetSymbolAddress((void**)&zl, g_zl);
    cudaGetSymbolAddress((void**)&w1h, g_w1h); cudaGetSymbolAddress((void**)&w1l, g_w1l);
    cudaGetSymbolAddress((void**)&w2h, g_w2h); cudaGetSymbolAddress((void**)&w2l, g_w2l);
    cudaGetSymbolAddress((void**)&wth, g_wth); cudaGetSymbolAddress((void**)&wtl, g_wtl);
    cudaGetSymbolAddress((void**)&wph, g_wph); cudaGetSymbolAddress((void**)&wpl, g_wpl);
    cudaGetSymbolAddress((void**)&zraw, g_zraw);
    cudaGetSymbolAddress((void**)&dot, g_dot);
    cudaGetSymbolAddress(&maxp, g_maxclass);

    auto* g1  = tc_gemm<IN_DIM / 64, true, true, true>;
    auto* g2  = tc_gemm<BELLY / 64, false, false, false>;
    auto* g34 = tc_gemm<SCALE_D / 64, true, false, false>;
    cudaFuncSetAttribute(g1,  cudaFuncAttributeMaxDynamicSharedMemorySize, SM_TOTAL);
    cudaFuncSetAttribute(g2,  cudaFuncAttributeMaxDynamicSharedMemorySize, SM_TOTAL);
    cudaFuncSetAttribute(g34, cudaFuncAttributeMaxDynamicSharedMemorySize, SM_TOTAL);

    cudaMemsetAsync(maxp, 0, sizeof(int), 0);
    k_maxclass<<<32, 256>>>(timesteps, BATCH);

    // prep: split features, pack weights
    {
        const int n4 = BATCH * IN_DIM / 4;
        k_split<<<(n4 + 255) / 256, 256>>>(features, fh, fl, n4);
        int t1 = (IN_DIM / 2) * 1024;
        k_pack<<<(t1 + 255) / 256, 256>>>(W1, w1h, w1l, BELLY, 1024, t1);
        int t2 = (BELLY / 2) * 512;
        k_pack<<<(t2 + 255) / 256, 256>>>(W2, w2h, w2l, SCALE_D, 512, t2);
        int t3 = (SCALE_D / 2) * 128;
        k_pack<<<(t3 + 255) / 256, 256>>>(Wt, wth, wtl, NBINS, 128, t3);
        int t4 = (SCALE_D / 2) * 1024;
        k_pack<<<(t4 + 255) / 256, 256>>>(Wp, wph, wpl, NBINS * NPAT, 1024, t4);
    }

    // GEMM1: h(split) = relu(features @ W1 + b1)
    g1<<<dim3(BELLY / 128, BATCH / 128), 256, SM_TOTAL>>>(
        fh, fl, w1h, w1l, b1, nullptr, hh, hl, BELLY, 1024);

    // GEMM2: zraw = h @ W2
    g2<<<dim3(SCALE_D / 128, BATCH / 128), 256, SM_TOTAL>>>(
        hh, hl, w2h, w2l, nullptr, zraw, nullptr, nullptr, SCALE_D, 512);

    k_norm<<<BATCH / 8, 256>>>(zraw, w_pos, out_z, zh, zl, dot);
    k_cantor<<<(BATCH + 255) / 256, 256>>>(dot, b_pos, alpha, timesteps, out_tc, out_cv);

    // GEMM3: timestep_logits = z @ Wt + bt
    g34<<<dim3(1, BATCH / 128), 256, SM_TOTAL>>>(
        zh, zl, wth, wtl, bt, out_tl, nullptr, nullptr, NBINS, 128);

    // GEMM4: pattern_logits = z @ Wp + bp
    g34<<<dim3(8, BATCH / 128), 256, SM_TOTAL>>>(
        zh, zl, wph, wpl, bp, out_pl, nullptr, nullptr, NBINS * NPAT, 1024);
}

// round 8
// speedup vs baseline: 3.1608x; 1.0058x over previous
#include <cuda_runtime.h>
#include <cuda_bf16.h>
#include <math.h>
#include <stdint.h>

// Problem constants
#define BATCH   16384
#define IN_DIM  1280
#define BELLY   1024
#define SCALE_D 512
#define NBINS   100
#define NPAT    10

// Output layout (float32, concatenated flattened tuple)
#define Z_OFF   ((size_t)0)
#define TL_OFF  ((size_t)BATCH * SCALE_D)
#define PL_OFF  (TL_OFF + (size_t)BATCH * NBINS)
#define TC_OFF  (PL_OFF + (size_t)BATCH * NBINS * NPAT)
#define CV_OFF  (TC_OFF + (size_t)BATCH)

#define XMINF 1e-6f
#define XMAXF ((float)(1.0 - 1e-6))

// ---------------------------------------------------------------------------
// Scratch (device globals: allocation-guard safe)
// ---------------------------------------------------------------------------
__device__ __nv_bfloat16 g_fh[(size_t)BATCH * IN_DIM];
__device__ __nv_bfloat16 g_fl[(size_t)BATCH * IN_DIM];
__device__ __nv_bfloat16 g_hh[(size_t)BATCH * BELLY];
__device__ __nv_bfloat16 g_hl[(size_t)BATCH * BELLY];
__device__ __nv_bfloat16 g_zh[(size_t)BATCH * SCALE_D];
__device__ __nv_bfloat16 g_zl[(size_t)BATCH * SCALE_D];
__device__ float         g_zraw[(size_t)BATCH * SCALE_D];
// n-major, k-pair-contiguous weight planes: u32[Npad][K/2]
__device__ uint32_t g_w1h[1024 * (IN_DIM / 2)];
__device__ uint32_t g_w1l[1024 * (IN_DIM / 2)];
__device__ uint32_t g_w2h[512 * (BELLY / 2)];
__device__ uint32_t g_w2l[512 * (BELLY / 2)];
__device__ uint32_t g_wth[128 * (SCALE_D / 2)];
__device__ uint32_t g_wtl[128 * (SCALE_D / 2)];
__device__ uint32_t g_wph[1024 * (SCALE_D / 2)];
__device__ uint32_t g_wpl[1024 * (SCALE_D / 2)];
__device__ double g_dot[BATCH];
__device__ int    g_maxclass;

// ---------------------------------------------------------------------------
// Helpers
// ---------------------------------------------------------------------------
__device__ __forceinline__ void mma16816(float* d, const uint32_t* a, const uint32_t* b) {
    asm volatile(
        "mma.sync.aligned.m16n8k16.row.col.f32.bf16.bf16.f32 "
        "{%0,%1,%2,%3}, {%4,%5,%6,%7}, {%8,%9}, {%0,%1,%2,%3};"
        : "+f"(d[0]), "+f"(d[1]), "+f"(d[2]), "+f"(d[3])
        : "r"(a[0]), "r"(a[1]), "r"(a[2]), "r"(a[3]), "r"(b[0]), "r"(b[1]));
}
#define LDSM4(r0, r1, r2, r3, addr) \
    asm volatile("ldmatrix.sync.aligned.m8n8.x4.shared.b16 {%0,%1,%2,%3}, [%4];" \
                 : "=r"(r0), "=r"(r1), "=r"(r2), "=r"(r3) : "r"(addr))

__device__ __forceinline__ void split2(float x, __nv_bfloat16& h, __nv_bfloat16& l) {
    h = __float2bfloat16(x);
    l = __float2bfloat16(x - __bfloat162float(h));
}
__device__ __forceinline__ uint64_t pack4bf(__nv_bfloat16 a, __nv_bfloat16 b,
                                            __nv_bfloat16 c, __nv_bfloat16 d) {
    union { __nv_bfloat16 h[4]; uint64_t u; } u;
    u.h[0] = a; u.h[1] = b; u.h[2] = c; u.h[3] = d;
    return u.u;
}
__device__ __forceinline__ uint32_t pack2bf(__nv_bfloat16 a, __nv_bfloat16 b) {
    union { __nv_bfloat16 h[2]; uint32_t u; } u;
    u.h[0] = a; u.h[1] = b;
    return u.u;
}
__device__ __forceinline__ uint32_t smem_u32(const void* p) {
    uint32_t a;
    asm("{ .reg .u64 t; cvta.to.shared.u64 t, %1; cvt.u32.u64 %0, t; }"
        : "=r"(a) : "l"(p));
    return a;
}
__device__ __forceinline__ void cp16(uint32_t dst, const void* src) {
    asm volatile("cp.async.cg.shared.global [%0], [%1], 16;"
                 :: "r"(dst), "l"(src));
}
#define CP_COMMIT() asm volatile("cp.async.commit_group;" ::: "memory")
#define CP_WAIT1()  asm volatile("cp.async.wait_group 1;" ::: "memory")
#define CP_WAIT0()  asm volatile("cp.async.wait_group 0;" ::: "memory")

// smem: all 4 planes are [128 rows][36 u32] (rows = m for A, n for B; cols = k-pairs + pad)
#define SROW_B 144               // bytes per row
#define PLANE  18432             // bytes per plane
#define OFF_AL PLANE
#define OFF_BH (2 * PLANE)
#define OFF_BL (3 * PLANE)
#define BUF_BYTES (4 * PLANE)    // 73728
#define SM_TOTAL (2 * BUF_BYTES) // 147456

// ---------------------------------------------------------------------------
// bf16 split GEMM on HMMA: C[M,Npad] = op(A@B + bias)
// A: pre-split bf16 planes [M][K]. B: pre-packed u32 planes [Npad][K/2].
// Tile 128x128, BK=64, 256 threads (8 warps = 4M x 2N), cp.async dbl buffer,
// ldmatrix fragment loads.
// ---------------------------------------------------------------------------
template<int KCHUNKS, bool BIAS, bool RELU, bool SPLIT_OUT>
__global__ __launch_bounds__(256)
void tc_gemm(const __nv_bfloat16* __restrict__ Ahi,
             const __nv_bfloat16* __restrict__ Alo,
             const uint32_t* __restrict__ Bh,
             const uint32_t* __restrict__ Bl,
             const float* __restrict__ bias,
             float* __restrict__ C,
             __nv_bfloat16* __restrict__ Chi,
             __nv_bfloat16* __restrict__ Clo,
             int N) {
    constexpr int K = KCHUNKS * 64;
    constexpr int KH = K / 2;
    extern __shared__ char smem[];
    const uint32_t sb = smem_u32(smem);

    const int tid = threadIdx.x, wid = tid >> 5, lid = tid & 31;
    const int gid = lid >> 2, tig = lid & 3;
    const int mw = (wid & 3) * 32;
    const int nw = (wid >> 2) * 64;
    const int m0 = blockIdx.y * 128, n0 = blockIdx.x * 128;

    // ldmatrix per-thread byte offsets within a plane
    uint32_t aoff[2], boff[4];
#pragma unroll
    for (int mat = 0; mat < 2; mat++) {
        const int r = mw + mat * 16 + (lid & 15);
        const int kc = (lid >> 4) * 4;               // u32
        aoff[mat] = (uint32_t)(r * 36 + kc) * 4;
    }
#pragma unroll
    for (int p = 0; p < 4; p++) {
        const int r = nw + p * 16 + (lid & 7) + ((lid & 16) >> 1);
        const int kc = ((lid >> 3) & 1) * 4;         // u32
        boff[p] = (uint32_t)(r * 36 + kc) * 4;
    }

    float acc[2][8][4];
#pragma unroll
    for (int i = 0; i < 2; i++)
#pragma unroll
        for (int j = 0; j < 8; j++)
#pragma unroll
            for (int q = 0; q < 4; q++) acc[i][j][q] = 0.0f;

    // ---- async fill of one chunk into buffer boffb
    auto fill = [&](int c, uint32_t boffb) {
        const int k0 = c * 64;
        // A planes: rows = m, 128 B payload per row (8 x 16B)
#pragma unroll
        for (int i = 0; i < 4; i++) {
            const int idx = tid + i * 256;
            const int row = idx >> 3, c8 = idx & 7;
            const uint32_t d = sb + boffb + row * SROW_B + c8 * 16;
            const size_t g = (size_t)(m0 + row) * K + k0 + c8 * 8;
            cp16(d, Ahi + g);
            cp16(d + OFF_AL, Alo + g);
        }
        // B planes: rows = n, 128 B payload per row
#pragma unroll
        for (int i = 0; i < 4; i++) {
            const int idx = tid + i * 256;
            const int row = idx >> 3, c8 = idx & 7;
            const uint32_t d = sb + boffb + OFF_BH + row * SROW_B + c8 * 16;
            const size_t g = (size_t)(n0 + row) * KH + (k0 >> 1) + c8 * 4;
            cp16(d, Bh + g);
            cp16(d + (OFF_BL - OFF_BH), Bl + g);
        }
    };

    fill(0, 0);
    CP_COMMIT();

    for (int c = 0; c < KCHUNKS; c++) {
        if (c + 1 < KCHUNKS) {
            fill(c + 1, (uint32_t)((c + 1) & 1) * BUF_BYTES);
            CP_COMMIT();
            CP_WAIT1();
        } else {
            CP_WAIT0();
        }
        __syncthreads();

        const uint32_t bufb = sb + (uint32_t)(c & 1) * BUF_BYTES;

#pragma unroll
        for (int ks = 0; ks < 4; ks++) {
            const uint32_t kbB = ks * 32;   // 8 u32 per kstep = 32 bytes
            uint32_t ah[2][4], al[2][4], bfh[8][2], bfl[8][2];
#pragma unroll
            for (int mat = 0; mat < 2; mat++) {
                LDSM4(ah[mat][0], ah[mat][1], ah[mat][2], ah[mat][3],
                      bufb + aoff[mat] + kbB);
                LDSM4(al[mat][0], al[mat][1], al[mat][2], al[mat][3],
                      bufb + OFF_AL + aoff[mat] + kbB);
            }
#pragma unroll
            for (int p = 0; p < 4; p++) {
                LDSM4(bfh[2 * p][0], bfh[2 * p][1], bfh[2 * p + 1][0], bfh[2 * p + 1][1],
                      bufb + OFF_BH + boff[p] + kbB);
                LDSM4(bfl[2 * p][0], bfl[2 * p][1], bfl[2 * p + 1][0], bfl[2 * p + 1][1],
                      bufb + OFF_BL + boff[p] + kbB);
            }
#pragma unroll
            for (int mat = 0; mat < 2; mat++)
#pragma unroll
                for (int nat = 0; nat < 8; nat++) {
                    mma16816(acc[mat][nat], ah[mat], bfh[nat]);
                    mma16816(acc[mat][nat], ah[mat], bfl[nat]);
                    mma16816(acc[mat][nat], al[mat], bfh[nat]);
                }
        }
        __syncthreads();   // reads done before this buffer is refilled
    }

    // ---- epilogue
#pragma unroll
    for (int mat = 0; mat < 2; mat++) {
        const int r0 = m0 + mw + mat * 16 + gid;
#pragma unroll
        for (int nat = 0; nat < 8; nat++) {
            const int n = n0 + nw + nat * 8 + tig * 2;
            float c0 = acc[mat][nat][0], c1 = acc[mat][nat][1];
            float c2 = acc[mat][nat][2], c3 = acc[mat][nat][3];
            if (BIAS) {
                const float bv0 = (n < N) ? bias[n] : 0.0f;
                const float bv1 = (n + 1 < N) ? bias[n + 1] : 0.0f;
                c0 += bv0; c1 += bv1; c2 += bv0; c3 += bv1;
            }
            if (RELU) {
                c0 = fmaxf(c0, 0.0f); c1 = fmaxf(c1, 0.0f);
                c2 = fmaxf(c2, 0.0f); c3 = fmaxf(c3, 0.0f);
            }
            if (SPLIT_OUT) {
                __nv_bfloat16 h0, l0, h1, l1;
                if (n + 1 < N) {
                    split2(c0, h0, l0); split2(c1, h1, l1);
                    *(uint32_t*)(Chi + (size_t)r0 * N + n) = pack2bf(h0, h1);
                    *(uint32_t*)(Clo + (size_t)r0 * N + n) = pack2bf(l0, l1);
                    split2(c2, h0, l0); split2(c3, h1, l1);
                    *(uint32_t*)(Chi + (size_t)(r0 + 8) * N + n) = pack2bf(h0, h1);
                    *(uint32_t*)(Clo + (size_t)(r0 + 8) * N + n) = pack2bf(l0, l1);
                } else if (n < N) {
                    split2(c0, h0, l0);
                    Chi[(size_t)r0 * N + n] = h0; Clo[(size_t)r0 * N + n] = l0;
                    split2(c2, h0, l0);
                    Chi[(size_t)(r0 + 8) * N + n] = h0; Clo[(size_t)(r0 + 8) * N + n] = l0;
                }
            } else {
                if (n + 1 < N) {
                    *(float2*)(C + (size_t)r0 * N + n) = make_float2(c0, c1);
                    *(float2*)(C + (size_t)(r0 + 8) * N + n) = make_float2(c2, c3);
                } else if (n < N) {
                    C[(size_t)r0 * N + n] = c0;
                    C[(size_t)(r0 + 8) * N + n] = c2;
                }
            }
        }
    }
}

// ---------------------------------------------------------------------------
// Prep kernels
// ---------------------------------------------------------------------------
__global__ void k_split(const float* __restrict__ x, __nv_bfloat16* __restrict__ xh,
                        __nv_bfloat16* __restrict__ xl, int n4) {
    const int i = blockIdx.x * blockDim.x + threadIdx.x;
    if (i >= n4) return;
    const float4 v = ((const float4*)x)[i];
    __nv_bfloat16 h0, l0, h1, l1, h2, l2, h3, l3;
    split2(v.x, h0, l0); split2(v.y, h1, l1);
    split2(v.z, h2, l2); split2(v.w, h3, l3);
    ((uint64_t*)xh)[i] = pack4bf(h0, h1, h2, h3);
    ((uint64_t*)xl)[i] = pack4bf(l0, l1, l2, l3);
}

// W [K][N] fp32 -> n-major k-pair packed u32 [Npad][K/2] hi/lo, zero padded
__global__ void k_pack(const float* __restrict__ W, uint32_t* __restrict__ Wh,
                       uint32_t* __restrict__ Wl, int N, int kh, int total) {
    const int idx = blockIdx.x * blockDim.x + threadIdx.x;
    if (idx >= total) return;
    const int n = idx / kh, kp = idx - n * kh;
    float v0 = 0.0f, v1 = 0.0f;
    if (n < N) {
        v0 = W[(size_t)(2 * kp) * N + n];
        v1 = W[(size_t)(2 * kp + 1) * N + n];
    }
    __nv_bfloat16 h0, l0, h1, l1;
    split2(v0, h0, l0); split2(v1, h1, l1);
    Wh[idx] = pack2bf(h0, h1);
    Wl[idx] = pack2bf(l0, l1);
}

// ---------------------------------------------------------------------------
// Exact timestep class + max reduction
// ---------------------------------------------------------------------------
__device__ __forceinline__ int ts_class(int ts) {
    int c = ts / 10;
    return min(max(c, 0), NBINS - 1);
}
__global__ void k_maxclass(const int* __restrict__ ts, int n) {
    int i = blockIdx.x * blockDim.x + threadIdx.x;
    int local = 0;
    for (; i < n; i += gridDim.x * blockDim.x)
        local = max(local, ts_class(ts[i]));
#pragma unroll
    for (int o = 16; o; o >>= 1)
        local = max(local, __shfl_xor_sync(0xffffffffu, local, o));
    if ((threadIdx.x & 31) == 0) atomicMax(&g_maxclass, local);
}

// ---------------------------------------------------------------------------
// Row normalize: one WARP per row; writes z (fp32), z splits (bf16), and dot.
// ---------------------------------------------------------------------------
__global__ __launch_bounds__(256)
void k_norm(const float* __restrict__ zraw,
            const float* __restrict__ w_pos,
            float* __restrict__ out_z,
            __nv_bfloat16* __restrict__ zh,
            __nv_bfloat16* __restrict__ zl,
            double* __restrict__ out_dot) {
    const int lid = threadIdx.x & 31;
    const int row = blockIdx.x * 8 + (threadIdx.x >> 5);

    const float4* zr = (const float4*)(zraw + (size_t)row * SCALE_D);
    const float4* wp = (const float4*)w_pos;

    float4 zv[4];
    float ss = 0.0f;
#pragma unroll
    for (int i = 0; i < 4; i++) {
        zv[i] = zr[lid + 32 * i];
        ss += zv[i].x * zv[i].x + zv[i].y * zv[i].y +
              zv[i].z * zv[i].z + zv[i].w * zv[i].w;
    }
#pragma unroll
    for (int o = 16; o; o >>= 1)
        ss += __shfl_xor_sync(0xffffffffu, ss, o);

    const float nrm = fmaxf(__fsqrt_rn(ss), 1e-12f);

    float4* zo = (float4*)(out_z + (size_t)row * SCALE_D);
    double dd = 0.0;
#pragma unroll
    for (int i = 0; i < 4; i++) {
        float4 o;
        const float4 wv = wp[lid + 32 * i];
        o.x = __fdiv_rn(zv[i].x, nrm);
        o.y = __fdiv_rn(zv[i].y, nrm);
        o.z = __fdiv_rn(zv[i].z, nrm);
        o.w = __fdiv_rn(zv[i].w, nrm);
        zo[lid + 32 * i] = o;
        __nv_bfloat16 h0, l0, h1, l1, h2, l2, h3, l3;
        split2(o.x, h0, l0); split2(o.y, h1, l1);
        split2(o.z, h2, l2); split2(o.w, h3, l3);
        const size_t e = (size_t)row * SCALE_D + (lid + 32 * i) * 4;
        *(uint64_t*)(zh + e) = pack4bf(h0, h1, h2, h3);
        *(uint64_t*)(zl + e) = pack4bf(l0, l1, l2, l3);
        dd += (double)o.x * wv.x + (double)o.y * wv.y +
              (double)o.z * wv.z + (double)o.w * wv.w;
    }
#pragma unroll
    for (int o = 16; o; o >>= 1)
        dd += __shfl_xor_sync(0xffffffffu, dd, o);

    if (lid == 0) out_dot[row] = dd;
}

// ---------------------------------------------------------------------------
// Cantor staircase: one THREAD per row. Numerics identical to passing R4/R6/R7.
// ---------------------------------------------------------------------------
__global__ __launch_bounds__(256)
void k_cantor(const double* __restrict__ dot,
              const float* __restrict__ b_pos,
              const float* __restrict__ alpha_p,
              const int* __restrict__ timesteps,
              float* __restrict__ out_tc,
              float* __restrict__ out_cv) {
    const int row = blockIdx.x * blockDim.x + threadIdx.x;
    if (row >= BATCH) return;

    const float tot_dd = (float)dot[row];
    const int cls = ts_class(timesteps[row]);

    const int max_pos = g_maxclass + 1;
    const float denom = (float)max(max_pos - 1, 1);
    const float pos_f = (float)cls;
    float x = (max_pos > 1) ? __fdiv_rn(pos_f, denom) : pos_f;
    x = fminf(fmaxf(x, XMINF), XMAXF);

    const float pre = __fadd_rn(tot_dd, b_pos[0]);
    const float shift = __fmul_rn((float)tanh((double)pre), 0.3f);
    x = fminf(fmaxf(__fadd_rn(x, shift), XMINF), XMAXF);

    const double alpha = (double)(*alpha_p);
    const float tau_d = __fadd_rn(0.25f, 1e-8f);
    double Cx = 0.0;
    double w = 0.5;
#pragma unroll
    for (int L = 0; L < 12; L++) {
        const float y = __fmul_rn(x, 3.0f);
        const float d0 = __fadd_rn(y, -0.5f);
        const float d1 = __fadd_rn(y, -1.5f);
        const float d2 = __fadd_rn(y, -2.5f);
        const float l0 = __fdiv_rn(-__fmul_rn(d0, d0), tau_d);
        const float l1 = __fdiv_rn(-__fmul_rn(d1, d1), tau_d);
        const float l2 = __fdiv_rn(-__fmul_rn(d2, d2), tau_d);
        const float m = fmaxf(l0, fmaxf(l1, l2));
        const double e0 = exp((double)__fadd_rn(l0, -m));
        const double e1 = exp((double)__fadd_rn(l1, -m));
        const double e2 = exp((double)__fadd_rn(l2, -m));
        const double inv_s = 1.0 / (e0 + e1 + e2);
        const double bit = e1 * inv_s * alpha + e2 * inv_s;
        Cx += bit * w;
        w *= 0.5;
        x = __fadd_rn(y, -floorf(y));
    }
    out_tc[row] = (float)cls;
    float cvf = (float)Cx;
    out_cv[row] = fminf(fmaxf(cvf, 0.0f), 1.0f);
}

// ---------------------------------------------------------------------------
// Launch  (order chosen so GEMM1 is the 6th launch -> ncu -s 5 -c 1 profiles it)
// ---------------------------------------------------------------------------
extern "C" void kernel_launch(void* const* d_in, const int* in_sizes, int n_in,
                              void* d_out, int out_size) {
    const float* features = (const float*)d_in[0];
    const int*   timesteps = (const int*)d_in[1];
    const float* W1    = (const float*)d_in[2];
    const float* b1    = (const float*)d_in[3];
    const float* W2    = (const float*)d_in[4];
    const float* Wt    = (const float*)d_in[5];
    const float* bt    = (const float*)d_in[6];
    const float* Wp    = (const float*)d_in[7];
    const float* bp    = (const float*)d_in[8];
    const float* w_pos = (const float*)d_in[9];
    const float* b_pos = (const float*)d_in[10];
    const float* alpha = (const float*)d_in[11];

    float* out = (float*)d_out;
    float* out_z  = out + Z_OFF;
    float* out_tl = out + TL_OFF;
    float* out_pl = out + PL_OFF;
    float* out_tc = out + TC_OFF;
    float* out_cv = out + CV_OFF;

    __nv_bfloat16 *fh, *fl, *hh, *hl, *zh, *zl;
    uint32_t *w1h, *w1l, *w2h, *w2l, *wth, *wtl, *wph, *wpl;
    float* zraw; double* dot; void* maxp;
    cudaGetSymbolAddress((void**)&fh, g_fh);   cudaGetSymbolAddress((void**)&fl, g_fl);
    cudaGetSymbolAddress((void**)&hh, g_hh);   cudaGetSymbolAddress((void**)&hl, g_hl);
    cudaGetSymbolAddress((void**)&zh, g_zh);   cudaGetSymbolAddress((void**)&zl, g_zl);
    cudaGetSymbolAddress((void**)&w1h, g_w1h); cudaGetSymbolAddress((void**)&w1l, g_w1l);
    cudaGetSymbolAddress((void**)&w2h, g_w2h); cudaGetSymbolAddress((void**)&w2l, g_w2l);
    cudaGetSymbolAddress((void**)&wth, g_wth); cudaGetSymbolAddress((void**)&wtl, g_wtl);
    cudaGetSymbolAddress((void**)&wph, g_wph); cudaGetSymbolAddress((void**)&wpl, g_wpl);
    cudaGetSymbolAddress((void**)&zraw, g_zraw);
    cudaGetSymbolAddress((void**)&dot, g_dot);
    cudaGetSymbolAddress(&maxp, g_maxclass);

    auto* g1  = tc_gemm<IN_DIM / 64, true, true, true>;
    auto* g2  = tc_gemm<BELLY / 64, false, false, false>;
    auto* g34 = tc_gemm<SCALE_D / 64, true, false, false>;
    cudaFuncSetAttribute(g1,  cudaFuncAttributeMaxDynamicSharedMemorySize, SM_TOTAL);
    cudaFuncSetAttribute(g2,  cudaFuncAttributeMaxDynamicSharedMemorySize, SM_TOTAL);
    cudaFuncSetAttribute(g34, cudaFuncAttributeMaxDynamicSharedMemorySize, SM_TOTAL);

    cudaMemsetAsync(maxp, 0, sizeof(int), 0);          // launch 1
    k_maxclass<<<32, 256>>>(timesteps, BATCH);         // launch 2

    const int n4 = BATCH * IN_DIM / 4;
    k_split<<<(n4 + 255) / 256, 256>>>(features, fh, fl, n4);   // 3
    const int t1 = 1024 * (IN_DIM / 2);
    k_pack<<<(t1 + 255) / 256, 256>>>(W1, w1h, w1l, BELLY, IN_DIM / 2, t1);   // 4
    const int t2 = 512 * (BELLY / 2);
    k_pack<<<(t2 + 255) / 256, 256>>>(W2, w2h, w2l, SCALE_D, BELLY / 2, t2);  // 5

    // GEMM1 (6th launch - profiled): h(split) = relu(features @ W1 + b1)
    g1<<<dim3(BELLY / 128, BATCH / 128), 256, SM_TOTAL>>>(
        fh, fl, w1h, w1l, b1, nullptr, hh, hl, BELLY);

    // GEMM2: zraw = h @ W2
    g2<<<dim3(SCALE_D / 128, BATCH / 128), 256, SM_TOTAL>>>(
        hh, hl, w2h, w2l, nullptr, zraw, nullptr, nullptr, SCALE_D);

    k_norm<<<BATCH / 8, 256>>>(zraw, w_pos, out_z, zh, zl, dot);
    k_cantor<<<(BATCH + 255) / 256, 256>>>(dot, b_pos, alpha, timesteps, out_tc, out_cv);

    const int t3 = 128 * (SCALE_D / 2);
    k_pack<<<(t3 + 255) / 256, 256>>>(Wt, wth, wtl, NBINS, SCALE_D / 2, t3);
    const int t4 = 1024 * (SCALE_D / 2);
    k_pack<<<(t4 + 255) / 256, 256>>>(Wp, wph, wpl, NBINS * NPAT, SCALE_D / 2, t4);

    // GEMM3: timestep_logits = z @ Wt + bt
    g34<<<dim3(1, BATCH / 128), 256, SM_TOTAL>>>(
        zh, zl, wth, wtl, bt, out_tl, nullptr, nullptr, NBINS);

    // GEMM4: pattern_logits = z @ Wp + bp
    g34<<<dim3(8, BATCH / 128), 256, SM_TOTAL>>>(
        zh, zl, wph, wpl, bp, out_pl, nullptr, nullptr, NBINS * NPAT);
}

// round 9
// speedup vs baseline: 3.2458x; 1.0269x over previous
#include <cuda_runtime.h>
#include <cuda_bf16.h>
#include <math.h>
#include <stdint.h>

// Problem constants
#define BATCH   16384
#define IN_DIM  1280
#define BELLY   1024
#define SCALE_D 512
#define NBINS   100
#define NPAT    10

// Output layout (float32, concatenated flattened tuple)
#define Z_OFF   ((size_t)0)
#define TL_OFF  ((size_t)BATCH * SCALE_D)
#define PL_OFF  (TL_OFF + (size_t)BATCH * NBINS)
#define TC_OFF  (PL_OFF + (size_t)BATCH * NBINS * NPAT)
#define CV_OFF  (TC_OFF + (size_t)BATCH)

#define XMINF 1e-6f
#define XMAXF ((float)(1.0 - 1e-6))

// ---------------------------------------------------------------------------
// Scratch (device globals: allocation-guard safe)
// ---------------------------------------------------------------------------
__device__ __nv_bfloat16 g_fh[(size_t)BATCH * IN_DIM];
__device__ __nv_bfloat16 g_fl[(size_t)BATCH * IN_DIM];
__device__ __nv_bfloat16 g_hh[(size_t)BATCH * BELLY];
__device__ __nv_bfloat16 g_hl[(size_t)BATCH * BELLY];
__device__ __nv_bfloat16 g_zh[(size_t)BATCH * SCALE_D];
__device__ __nv_bfloat16 g_zl[(size_t)BATCH * SCALE_D];
__device__ float         g_zraw[(size_t)BATCH * SCALE_D];
// n-major, k-pair-contiguous weight planes: u32[Npad][K/2]
__device__ uint32_t g_w1h[1024 * (IN_DIM / 2)];
__device__ uint32_t g_w1l[1024 * (IN_DIM / 2)];
__device__ uint32_t g_w2h[512 * (BELLY / 2)];
__device__ uint32_t g_w2l[512 * (BELLY / 2)];
__device__ uint32_t g_wth[128 * (SCALE_D / 2)];
__device__ uint32_t g_wtl[128 * (SCALE_D / 2)];
__device__ uint32_t g_wph[1024 * (SCALE_D / 2)];
__device__ uint32_t g_wpl[1024 * (SCALE_D / 2)];
__device__ double g_dot[BATCH];
__device__ int    g_maxclass;

// ---------------------------------------------------------------------------
// Helpers
// ---------------------------------------------------------------------------
__device__ __forceinline__ void mma16816(float* d, const uint32_t* a, const uint32_t* b) {
    asm volatile(
        "mma.sync.aligned.m16n8k16.row.col.f32.bf16.bf16.f32 "
        "{%0,%1,%2,%3}, {%4,%5,%6,%7}, {%8,%9}, {%0,%1,%2,%3};"
        : "+f"(d[0]), "+f"(d[1]), "+f"(d[2]), "+f"(d[3])
        : "r"(a[0]), "r"(a[1]), "r"(a[2]), "r"(a[3]), "r"(b[0]), "r"(b[1]));
}
#define LDSM4(r0, r1, r2, r3, addr) \
    asm volatile("ldmatrix.sync.aligned.m8n8.x4.shared.b16 {%0,%1,%2,%3}, [%4];" \
                 : "=r"(r0), "=r"(r1), "=r"(r2), "=r"(r3) : "r"(addr))

__device__ __forceinline__ void split2(float x, __nv_bfloat16& h, __nv_bfloat16& l) {
    h = __float2bfloat16(x);
    l = __float2bfloat16(x - __bfloat162float(h));
}
__device__ __forceinline__ uint64_t pack4bf(__nv_bfloat16 a, __nv_bfloat16 b,
                                            __nv_bfloat16 c, __nv_bfloat16 d) {
    union { __nv_bfloat16 h[4]; uint64_t u; } u;
    u.h[0] = a; u.h[1] = b; u.h[2] = c; u.h[3] = d;
    return u.u;
}
__device__ __forceinline__ uint32_t pack2bf(__nv_bfloat16 a, __nv_bfloat16 b) {
    union { __nv_bfloat16 h[2]; uint32_t u; } u;
    u.h[0] = a; u.h[1] = b;
    return u.u;
}
__device__ __forceinline__ uint32_t smem_u32(const void* p) {
    uint32_t a;
    asm("{ .reg .u64 t; cvta.to.shared.u64 t, %1; cvt.u32.u64 %0, t; }"
        : "=r"(a) : "l"(p));
    return a;
}
__device__ __forceinline__ void cp16(uint32_t dst, const void* src) {
    asm volatile("cp.async.cg.shared.global [%0], [%1], 16;"
                 :: "r"(dst), "l"(src));
}
#define CP_COMMIT() asm volatile("cp.async.commit_group;" ::: "memory")
#define CP_WAIT1()  asm volatile("cp.async.wait_group 1;" ::: "memory")
#define CP_WAIT0()  asm volatile("cp.async.wait_group 0;" ::: "memory")

// smem: all 4 planes are [128 rows][36 u32] (rows = m for A, n for B)
#define SROW_B 144               // bytes per row
#define PLANE  18432             // bytes per plane
#define OFF_AL PLANE
#define OFF_BH (2 * PLANE)
#define OFF_BL (3 * PLANE)
#define BUF_BYTES (4 * PLANE)    // 73728
#define SM_TOTAL (2 * BUF_BYTES) // 147456

#define NTHREADS 512

// ---------------------------------------------------------------------------
// bf16 split GEMM on HMMA: C[M,Npad] = op(A@B + bias)
// A: pre-split bf16 planes [M][K]. B: pre-packed u32 planes [Npad][K/2].
// Tile 128x128, BK=64, 512 threads (16 warps = 4M x 4N, warp tile 32x32),
// cp.async double buffer, ldmatrix fragment loads.
// ---------------------------------------------------------------------------
template<int KCHUNKS, bool BIAS, bool RELU, bool SPLIT_OUT>
__global__ __launch_bounds__(NTHREADS)
void tc_gemm(const __nv_bfloat16* __restrict__ Ahi,
             const __nv_bfloat16* __restrict__ Alo,
             const uint32_t* __restrict__ Bh,
             const uint32_t* __restrict__ Bl,
             const float* __restrict__ bias,
             float* __restrict__ C,
             __nv_bfloat16* __restrict__ Chi,
             __nv_bfloat16* __restrict__ Clo,
             int N) {
    constexpr int K = KCHUNKS * 64;
    constexpr int KH = K / 2;
    extern __shared__ char smem[];
    const uint32_t sb = smem_u32(smem);

    const int tid = threadIdx.x, wid = tid >> 5, lid = tid & 31;
    const int gid = lid >> 2, tig = lid & 3;
    const int mw = (wid & 3) * 32;      // warp M offset (4 warps over 128)
    const int nw = (wid >> 2) * 32;     // warp N offset (4 warps over 128)
    const int m0 = blockIdx.y * 128, n0 = blockIdx.x * 128;

    // ldmatrix per-thread byte offsets within a plane
    uint32_t aoff[2], boff[2];
#pragma unroll
    for (int mat = 0; mat < 2; mat++) {
        const int r = mw + mat * 16 + (lid & 15);
        const int kc = (lid >> 4) * 4;               // u32
        aoff[mat] = (uint32_t)(r * 36 + kc) * 4;
    }
#pragma unroll
    for (int p = 0; p < 2; p++) {
        const int r = nw + p * 16 + (lid & 7) + ((lid & 16) >> 1);
        const int kc = ((lid >> 3) & 1) * 4;         // u32
        boff[p] = (uint32_t)(r * 36 + kc) * 4;
    }

    float acc[2][4][4];
#pragma unroll
    for (int i = 0; i < 2; i++)
#pragma unroll
        for (int j = 0; j < 4; j++)
#pragma unroll
            for (int q = 0; q < 4; q++) acc[i][j][q] = 0.0f;

    // ---- async fill of one chunk into buffer boffb
    auto fill = [&](int c, uint32_t boffb) {
        const int k0 = c * 64;
        // A planes: rows = m, 128 B payload per row (8 x 16B)
#pragma unroll
        for (int i = 0; i < 2; i++) {
            const int idx = tid + i * NTHREADS;
            const int row = idx >> 3, c8 = idx & 7;
            const uint32_t d = sb + boffb + row * SROW_B + c8 * 16;
            const size_t g = (size_t)(m0 + row) * K + k0 + c8 * 8;
            cp16(d, Ahi + g);
            cp16(d + OFF_AL, Alo + g);
        }
        // B planes: rows = n, 128 B payload per row
#pragma unroll
        for (int i = 0; i < 2; i++) {
            const int idx = tid + i * NTHREADS;
            const int row = idx >> 3, c8 = idx & 7;
            const uint32_t d = sb + boffb + OFF_BH + row * SROW_B + c8 * 16;
            const size_t g = (size_t)(n0 + row) * KH + (k0 >> 1) + c8 * 4;
            cp16(d, Bh + g);
            cp16(d + (OFF_BL - OFF_BH), Bl + g);
        }
    };

    fill(0, 0);
    CP_COMMIT();

    for (int c = 0; c < KCHUNKS; c++) {
        if (c + 1 < KCHUNKS) {
            fill(c + 1, (uint32_t)((c + 1) & 1) * BUF_BYTES);
            CP_COMMIT();
            CP_WAIT1();
        } else {
            CP_WAIT0();
        }
        __syncthreads();

        const uint32_t bufb = sb + (uint32_t)(c & 1) * BUF_BYTES;

#pragma unroll
        for (int ks = 0; ks < 4; ks++) {
            const uint32_t kbB = ks * 32;   // 8 u32 per kstep = 32 bytes
            uint32_t ah[2][4], al[2][4], bfh[4][2], bfl[4][2];
#pragma unroll
            for (int mat = 0; mat < 2; mat++) {
                LDSM4(ah[mat][0], ah[mat][1], ah[mat][2], ah[mat][3],
                      bufb + aoff[mat] + kbB);
                LDSM4(al[mat][0], al[mat][1], al[mat][2], al[mat][3],
                      bufb + OFF_AL + aoff[mat] + kbB);
            }
#pragma unroll
            for (int p = 0; p < 2; p++) {
                LDSM4(bfh[2 * p][0], bfh[2 * p][1], bfh[2 * p + 1][0], bfh[2 * p + 1][1],
                      bufb + OFF_BH + boff[p] + kbB);
                LDSM4(bfl[2 * p][0], bfl[2 * p][1], bfl[2 * p + 1][0], bfl[2 * p + 1][1],
                      bufb + OFF_BL + boff[p] + kbB);
            }
#pragma unroll
            for (int mat = 0; mat < 2; mat++)
#pragma unroll
                for (int nat = 0; nat < 4; nat++) {
                    mma16816(acc[mat][nat], ah[mat], bfh[nat]);
                    mma16816(acc[mat][nat], ah[mat], bfl[nat]);
                    mma16816(acc[mat][nat], al[mat], bfh[nat]);
                }
        }
        __syncthreads();   // reads done before this buffer is refilled
    }

    // ---- epilogue
#pragma unroll
    for (int mat = 0; mat < 2; mat++) {
        const int r0 = m0 + mw + mat * 16 + gid;
#pragma unroll
        for (int nat = 0; nat < 4; nat++) {
            const int n = n0 + nw + nat * 8 + tig * 2;
            float c0 = acc[mat][nat][0], c1 = acc[mat][nat][1];
            float c2 = acc[mat][nat][2], c3 = acc[mat][nat][3];
            if (BIAS) {
                const float bv0 = (n < N) ? bias[n] : 0.0f;
                const float bv1 = (n + 1 < N) ? bias[n + 1] : 0.0f;
                c0 += bv0; c1 += bv1; c2 += bv0; c3 += bv1;
            }
            if (RELU) {
                c0 = fmaxf(c0, 0.0f); c1 = fmaxf(c1, 0.0f);
                c2 = fmaxf(c2, 0.0f); c3 = fmaxf(c3, 0.0f);
            }
            if (SPLIT_OUT) {
                __nv_bfloat16 h0, l0, h1, l1;
                if (n + 1 < N) {
                    split2(c0, h0, l0); split2(c1, h1, l1);
                    *(uint32_t*)(Chi + (size_t)r0 * N + n) = pack2bf(h0, h1);
                    *(uint32_t*)(Clo + (size_t)r0 * N + n) = pack2bf(l0, l1);
                    split2(c2, h0, l0); split2(c3, h1, l1);
                    *(uint32_t*)(Chi + (size_t)(r0 + 8) * N + n) = pack2bf(h0, h1);
                    *(uint32_t*)(Clo + (size_t)(r0 + 8) * N + n) = pack2bf(l0, l1);
                } else if (n < N) {
                    split2(c0, h0, l0);
                    Chi[(size_t)r0 * N + n] = h0; Clo[(size_t)r0 * N + n] = l0;
                    split2(c2, h0, l0);
                    Chi[(size_t)(r0 + 8) * N + n] = h0; Clo[(size_t)(r0 + 8) * N + n] = l0;
                }
            } else {
                if (n + 1 < N) {
                    *(float2*)(C + (size_t)r0 * N + n) = make_float2(c0, c1);
                    *(float2*)(C + (size_t)(r0 + 8) * N + n) = make_float2(c2, c3);
                } else if (n < N) {
                    C[(size_t)r0 * N + n] = c0;
                    C[(size_t)(r0 + 8) * N + n] = c2;
                }
            }
        }
    }
}

// ---------------------------------------------------------------------------
// Prep kernels
// ---------------------------------------------------------------------------
__global__ void k_split(const float* __restrict__ x, __nv_bfloat16* __restrict__ xh,
                        __nv_bfloat16* __restrict__ xl, int n4) {
    const int i = blockIdx.x * blockDim.x + threadIdx.x;
    if (i >= n4) return;
    const float4 v = ((const float4*)x)[i];
    __nv_bfloat16 h0, l0, h1, l1, h2, l2, h3, l3;
    split2(v.x, h0, l0); split2(v.y, h1, l1);
    split2(v.z, h2, l2); split2(v.w, h3, l3);
    ((uint64_t*)xh)[i] = pack4bf(h0, h1, h2, h3);
    ((uint64_t*)xl)[i] = pack4bf(l0, l1, l2, l3);
}

// W [K][N] fp32 -> n-major k-pair packed u32 [Npad][K/2] hi/lo, zero padded
__global__ void k_pack(const float* __restrict__ W, uint32_t* __restrict__ Wh,
                       uint32_t* __restrict__ Wl, int N, int kh, int total) {
    const int idx = blockIdx.x * blockDim.x + threadIdx.x;
    if (idx >= total) return;
    const int n = idx / kh, kp = idx - n * kh;
    float v0 = 0.0f, v1 = 0.0f;
    if (n < N) {
        v0 = W[(size_t)(2 * kp) * N + n];
        v1 = W[(size_t)(2 * kp + 1) * N + n];
    }
    __nv_bfloat16 h0, l0, h1, l1;
    split2(v0, h0, l0); split2(v1, h1, l1);
    Wh[idx] = pack2bf(h0, h1);
    Wl[idx] = pack2bf(l0, l1);
}

// ---------------------------------------------------------------------------
// Exact timestep class + max reduction
// ---------------------------------------------------------------------------
__device__ __forceinline__ int ts_class(int ts) {
    int c = ts / 10;
    return min(max(c, 0), NBINS - 1);
}
__global__ void k_maxclass(const int* __restrict__ ts, int n) {
    int i = blockIdx.x * blockDim.x + threadIdx.x;
    int local = 0;
    for (; i < n; i += gridDim.x * blockDim.x)
        local = max(local, ts_class(ts[i]));
#pragma unroll
    for (int o = 16; o; o >>= 1)
        local = max(local, __shfl_xor_sync(0xffffffffu, local, o));
    if ((threadIdx.x & 31) == 0) atomicMax(&g_maxclass, local);
}

// ---------------------------------------------------------------------------
// Row normalize: one WARP per row; writes z (fp32), z splits (bf16), and dot.
// ---------------------------------------------------------------------------
__global__ __launch_bounds__(256)
void k_norm(const float* __restrict__ zraw,
            const float* __restrict__ w_pos,
            float* __restrict__ out_z,
            __nv_bfloat16* __restrict__ zh,
            __nv_bfloat16* __restrict__ zl,
            double* __restrict__ out_dot) {
    const int lid = threadIdx.x & 31;
    const int row = blockIdx.x * 8 + (threadIdx.x >> 5);

    const float4* zr = (const float4*)(zraw + (size_t)row * SCALE_D);
    const float4* wp = (const float4*)w_pos;

    float4 zv[4];
    float ss = 0.0f;
#pragma unroll
    for (int i = 0; i < 4; i++) {
        zv[i] = zr[lid + 32 * i];
        ss += zv[i].x * zv[i].x + zv[i].y * zv[i].y +
              zv[i].z * zv[i].z + zv[i].w * zv[i].w;
    }
#pragma unroll
    for (int o = 16; o; o >>= 1)
        ss += __shfl_xor_sync(0xffffffffu, ss, o);

    const float nrm = fmaxf(__fsqrt_rn(ss), 1e-12f);

    float4* zo = (float4*)(out_z + (size_t)row * SCALE_D);
    double dd = 0.0;
#pragma unroll
    for (int i = 0; i < 4; i++) {
        float4 o;
        const float4 wv = wp[lid + 32 * i];
        o.x = __fdiv_rn(zv[i].x, nrm);
        o.y = __fdiv_rn(zv[i].y, nrm);
        o.z = __fdiv_rn(zv[i].z, nrm);
        o.w = __fdiv_rn(zv[i].w, nrm);
        zo[lid + 32 * i] = o;
        __nv_bfloat16 h0, l0, h1, l1, h2, l2, h3, l3;
        split2(o.x, h0, l0); split2(o.y, h1, l1);
        split2(o.z, h2, l2); split2(o.w, h3, l3);
        const size_t e = (size_t)row * SCALE_D + (lid + 32 * i) * 4;
        *(uint64_t*)(zh + e) = pack4bf(h0, h1, h2, h3);
        *(uint64_t*)(zl + e) = pack4bf(l0, l1, l2, l3);
        dd += (double)o.x * wv.x + (double)o.y * wv.y +
              (double)o.z * wv.z + (double)o.w * wv.w;
    }
#pragma unroll
    for (int o = 16; o; o >>= 1)
        dd += __shfl_xor_sync(0xffffffffu, dd, o);

    if (lid == 0) out_dot[row] = dd;
}

// ---------------------------------------------------------------------------
// Cantor staircase: one THREAD per row. Numerics identical since R4.
// ---------------------------------------------------------------------------
__global__ __launch_bounds__(256)
void k_cantor(const double* __restrict__ dot,
              const float* __restrict__ b_pos,
              const float* __restrict__ alpha_p,
              const int* __restrict__ timesteps,
              float* __restrict__ out_tc,
              float* __restrict__ out_cv) {
    const int row = blockIdx.x * blockDim.x + threadIdx.x;
    if (row >= BATCH) return;

    const float tot_dd = (float)dot[row];
    const int cls = ts_class(timesteps[row]);

    const int max_pos = g_maxclass + 1;
    const float denom = (float)max(max_pos - 1, 1);
    const float pos_f = (float)cls;
    float x = (max_pos > 1) ? __fdiv_rn(pos_f, denom) : pos_f;
    x = fminf(fmaxf(x, XMINF), XMAXF);

    const float pre = __fadd_rn(tot_dd, b_pos[0]);
    const float shift = __fmul_rn((float)tanh((double)pre), 0.3f);
    x = fminf(fmaxf(__fadd_rn(x, shift), XMINF), XMAXF);

    const double alpha = (double)(*alpha_p);
    const float tau_d = __fadd_rn(0.25f, 1e-8f);
    double Cx = 0.0;
    double w = 0.5;
#pragma unroll
    for (int L = 0; L < 12; L++) {
        const float y = __fmul_rn(x, 3.0f);
        const float d0 = __fadd_rn(y, -0.5f);
        const float d1 = __fadd_rn(y, -1.5f);
        const float d2 = __fadd_rn(y, -2.5f);
        const float l0 = __fdiv_rn(-__fmul_rn(d0, d0), tau_d);
        const float l1 = __fdiv_rn(-__fmul_rn(d1, d1), tau_d);
        const float l2 = __fdiv_rn(-__fmul_rn(d2, d2), tau_d);
        const float m = fmaxf(l0, fmaxf(l1, l2));
        const double e0 = exp((double)__fadd_rn(l0, -m));
        const double e1 = exp((double)__fadd_rn(l1, -m));
        const double e2 = exp((double)__fadd_rn(l2, -m));
        const double inv_s = 1.0 / (e0 + e1 + e2);
        const double bit = e1 * inv_s * alpha + e2 * inv_s;
        Cx += bit * w;
        w *= 0.5;
        x = __fadd_rn(y, -floorf(y));
    }
    out_tc[row] = (float)cls;
    float cvf = (float)Cx;
    out_cv[row] = fminf(fmaxf(cvf, 0.0f), 1.0f);
}

// ---------------------------------------------------------------------------
// Launch
// ---------------------------------------------------------------------------
extern "C" void kernel_launch(void* const* d_in, const int* in_sizes, int n_in,
                              void* d_out, int out_size) {
    const float* features = (const float*)d_in[0];
    const int*   timesteps = (const int*)d_in[1];
    const float* W1    = (const float*)d_in[2];
    const float* b1    = (const float*)d_in[3];
    const float* W2    = (const float*)d_in[4];
    const float* Wt    = (const float*)d_in[5];
    const float* bt    = (const float*)d_in[6];
    const float* Wp    = (const float*)d_in[7];
    const float* bp    = (const float*)d_in[8];
    const float* w_pos = (const float*)d_in[9];
    const float* b_pos = (const float*)d_in[10];
    const float* alpha = (const float*)d_in[11];

    float* out = (float*)d_out;
    float* out_z  = out + Z_OFF;
    float* out_tl = out + TL_OFF;
    float* out_pl = out + PL_OFF;
    float* out_tc = out + TC_OFF;
    float* out_cv = out + CV_OFF;

    __nv_bfloat16 *fh, *fl, *hh, *hl, *zh, *zl;
    uint32_t *w1h, *w1l, *w2h, *w2l, *wth, *wtl, *wph, *wpl;
    float* zraw; double* dot; void* maxp;
    cudaGetSymbolAddress((void**)&fh, g_fh);   cudaGetSymbolAddress((void**)&fl, g_fl);
    cudaGetSymbolAddress((void**)&hh, g_hh);   cudaGetSymbolAddress((void**)&hl, g_hl);
    cudaGetSymbolAddress((void**)&zh, g_zh);   cudaGetSymbolAddress((void**)&zl, g_zl);
    cudaGetSymbolAddress((void**)&w1h, g_w1h); cudaGetSymbolAddress((void**)&w1l, g_w1l);
    cudaGetSymbolAddress((void**)&w2h, g_w2h); cudaGetSymbolAddress((void**)&w2l, g_w2l);
    cudaGetSymbolAddress((void**)&wth, g_wth); cudaGetSymbolAddress((void**)&wtl, g_wtl);
    cudaGetSymbolAddress((void**)&wph, g_wph); cudaGetSymbolAddress((void**)&wpl, g_wpl);
    cudaGetSymbolAddress((void**)&zraw, g_zraw);
    cudaGetSymbolAddress((void**)&dot, g_dot);
    cudaGetSymbolAddress(&maxp, g_maxclass);

    auto* g1  = tc_gemm<IN_DIM / 64, true, true, true>;
    auto* g2  = tc_gemm<BELLY / 64, false, false, false>;
    auto* g34 = tc_gemm<SCALE_D / 64, true, false, false>;
    cudaFuncSetAttribute(g1,  cudaFuncAttributeMaxDynamicSharedMemorySize, SM_TOTAL);
    cudaFuncSetAttribute(g2,  cudaFuncAttributeMaxDynamicSharedMemorySize, SM_TOTAL);
    cudaFuncSetAttribute(g34, cudaFuncAttributeMaxDynamicSharedMemorySize, SM_TOTAL);

    cudaMemsetAsync(maxp, 0, sizeof(int), 0);
    k_maxclass<<<32, 256>>>(timesteps, BATCH);

    const int n4 = BATCH * IN_DIM / 4;
    k_split<<<(n4 + 255) / 256, 256>>>(features, fh, fl, n4);
    const int t1 = 1024 * (IN_DIM / 2);
    k_pack<<<(t1 + 255) / 256, 256>>>(W1, w1h, w1l, BELLY, IN_DIM / 2, t1);
    const int t2 = 512 * (BELLY / 2);
    k_pack<<<(t2 + 255) / 256, 256>>>(W2, w2h, w2l, SCALE_D, BELLY / 2, t2);

    // GEMM1: h(split) = relu(features @ W1 + b1)
    g1<<<dim3(BELLY / 128, BATCH / 128), NTHREADS, SM_TOTAL>>>(
        fh, fl, w1h, w1l, b1, nullptr, hh, hl, BELLY);

    // GEMM2: zraw = h @ W2
    g2<<<dim3(SCALE_D / 128, BATCH / 128), NTHREADS, SM_TOTAL>>>(
        hh, hl, w2h, w2l, nullptr, zraw, nullptr, nullptr, SCALE_D);

    k_norm<<<BATCH / 8, 256>>>(zraw, w_pos, out_z, zh, zl, dot);
    k_cantor<<<(BATCH + 255) / 256, 256>>>(dot, b_pos, alpha, timesteps, out_tc, out_cv);

    const int t3 = 128 * (SCALE_D / 2);
    k_pack<<<(t3 + 255) / 256, 256>>>(Wt, wth, wtl, NBINS, SCALE_D / 2, t3);
    const int t4 = 1024 * (SCALE_D / 2);
    k_pack<<<(t4 + 255) / 256, 256>>>(Wp, wph, wpl, NBINS * NPAT, SCALE_D / 2, t4);

    // GEMM3: timestep_logits = z @ Wt + bt
    g34<<<dim3(1, BATCH / 128), NTHREADS, SM_TOTAL>>>(
        zh, zl, wth, wtl, bt, out_tl, nullptr, nullptr, NBINS);

    // GEMM4: pattern_logits = z @ Wp + bp
    g34<<<dim3(8, BATCH / 128), NTHREADS, SM_TOTAL>>>(
        zh, zl, wph, wpl, bp, out_pl, nullptr, nullptr, NBINS * NPAT);
}

// round 10
// speedup vs baseline: 3.4120x; 1.0512x over previous
#include <cuda_runtime.h>
#include <cuda_bf16.h>
#include <math.h>
#include <stdint.h>

// Problem constants
#define BATCH   16384
#define IN_DIM  1280
#define BELLY   1024
#define SCALE_D 512
#define NBINS   100
#define NPAT    10
#define NCAT    1152   // 128 (Wt slot) + 1024 (Wp slot)

// Output layout (float32, concatenated flattened tuple)
#define Z_OFF   ((size_t)0)
#define TL_OFF  ((size_t)BATCH * SCALE_D)
#define PL_OFF  (TL_OFF + (size_t)BATCH * NBINS)
#define TC_OFF  (PL_OFF + (size_t)BATCH * NBINS * NPAT)
#define CV_OFF  (TC_OFF + (size_t)BATCH)

#define XMINF 1e-6f
#define XMAXF ((float)(1.0 - 1e-6))

// ---------------------------------------------------------------------------
// Scratch (device globals: allocation-guard safe)
// ---------------------------------------------------------------------------
__device__ __nv_bfloat16 g_fh[(size_t)BATCH * IN_DIM];
__device__ __nv_bfloat16 g_fl[(size_t)BATCH * IN_DIM];
__device__ __nv_bfloat16 g_hh[(size_t)BATCH * BELLY];
__device__ __nv_bfloat16 g_hl[(size_t)BATCH * BELLY];
__device__ __nv_bfloat16 g_zh[(size_t)BATCH * SCALE_D];
__device__ __nv_bfloat16 g_zl[(size_t)BATCH * SCALE_D];
__device__ float         g_zraw[(size_t)BATCH * SCALE_D];
// n-major, k-pair-contiguous weight planes: u32[Npad][K/2]
__device__ uint32_t g_w1h[1024 * (IN_DIM / 2)];
__device__ uint32_t g_w1l[1024 * (IN_DIM / 2)];
__device__ uint32_t g_w2h[512 * (BELLY / 2)];
__device__ uint32_t g_w2l[512 * (BELLY / 2)];
__device__ uint32_t g_wch[NCAT * (SCALE_D / 2)];   // concat Wt|Wp
__device__ uint32_t g_wcl[NCAT * (SCALE_D / 2)];
__device__ float    g_bcat[NCAT];
__device__ float    g_dot[BATCH];
__device__ int      g_maxclass;

// ---------------------------------------------------------------------------
// Helpers
// ---------------------------------------------------------------------------
__device__ __forceinline__ void mma16816(float* d, const uint32_t* a, const uint32_t* b) {
    asm volatile(
        "mma.sync.aligned.m16n8k16.row.col.f32.bf16.bf16.f32 "
        "{%0,%1,%2,%3}, {%4,%5,%6,%7}, {%8,%9}, {%0,%1,%2,%3};"
        : "+f"(d[0]), "+f"(d[1]), "+f"(d[2]), "+f"(d[3])
        : "r"(a[0]), "r"(a[1]), "r"(a[2]), "r"(a[3]), "r"(b[0]), "r"(b[1]));
}
#define LDSM4(r0, r1, r2, r3, addr) \
    asm volatile("ldmatrix.sync.aligned.m8n8.x4.shared.b16 {%0,%1,%2,%3}, [%4];" \
                 : "=r"(r0), "=r"(r1), "=r"(r2), "=r"(r3) : "r"(addr))

__device__ __forceinline__ void split2(float x, __nv_bfloat16& h, __nv_bfloat16& l) {
    h = __float2bfloat16(x);
    l = __float2bfloat16(x - __bfloat162float(h));
}
__device__ __forceinline__ uint64_t pack4bf(__nv_bfloat16 a, __nv_bfloat16 b,
                                            __nv_bfloat16 c, __nv_bfloat16 d) {
    union { __nv_bfloat16 h[4]; uint64_t u; } u;
    u.h[0] = a; u.h[1] = b; u.h[2] = c; u.h[3] = d;
    return u.u;
}
__device__ __forceinline__ uint32_t pack2bf(__nv_bfloat16 a, __nv_bfloat16 b) {
    union { __nv_bfloat16 h[2]; uint32_t u; } u;
    u.h[0] = a; u.h[1] = b;
    return u.u;
}
__device__ __forceinline__ uint32_t smem_u32(const void* p) {
    uint32_t a;
    asm("{ .reg .u64 t; cvta.to.shared.u64 t, %1; cvt.u32.u64 %0, t; }"
        : "=r"(a) : "l"(p));
    return a;
}
__device__ __forceinline__ void cp16(uint32_t dst, const void* src) {
    asm volatile("cp.async.cg.shared.global [%0], [%1], 16;"
                 :: "r"(dst), "l"(src));
}
#define CP_COMMIT() asm volatile("cp.async.commit_group;" ::: "memory")
#define CP_WAIT1()  asm volatile("cp.async.wait_group 1;" ::: "memory")
#define CP_WAIT0()  asm volatile("cp.async.wait_group 0;" ::: "memory")

// smem: all 4 planes are [128 rows][36 u32] (rows = m for A, n for B)
#define SROW_B 144               // bytes per row
#define PLANE  18432             // bytes per plane
#define OFF_AL PLANE
#define OFF_BH (2 * PLANE)
#define OFF_BL (3 * PLANE)
#define BUF_BYTES (4 * PLANE)    // 73728
#define SM_TOTAL (2 * BUF_BYTES) // 147456

#define NTHREADS 512

// ---------------------------------------------------------------------------
// bf16 split GEMM on HMMA: C[M,Npad] = op(A@B + bias)
// A: pre-split bf16 planes [M][K]. B: pre-packed u32 planes [Npad][K/2].
// Tile 128x128, BK=64, 512 threads (16 warps = 4M x 4N, warp tile 32x32).
// FUSE: epilogue routes concat columns (0-127 -> Ctl[...,100], 128+ -> Cpl[...,1000]).
// ---------------------------------------------------------------------------
template<int KCHUNKS, bool BIAS, bool RELU, bool SPLIT_OUT, bool FUSE>
__global__ __launch_bounds__(NTHREADS)
void tc_gemm(const __nv_bfloat16* __restrict__ Ahi,
             const __nv_bfloat16* __restrict__ Alo,
             const uint32_t* __restrict__ Bh,
             const uint32_t* __restrict__ Bl,
             const float* __restrict__ bias,
             float* __restrict__ C,
             float* __restrict__ Cpl,
             __nv_bfloat16* __restrict__ Chi,
             __nv_bfloat16* __restrict__ Clo,
             int N) {
    constexpr int K = KCHUNKS * 64;
    constexpr int KH = K / 2;
    extern __shared__ char smem[];
    const uint32_t sb = smem_u32(smem);

    const int tid = threadIdx.x, wid = tid >> 5, lid = tid & 31;
    const int gid = lid >> 2, tig = lid & 3;
    const int mw = (wid & 3) * 32;
    const int nw = (wid >> 2) * 32;
    const int m0 = blockIdx.y * 128, n0 = blockIdx.x * 128;

    // ldmatrix per-thread byte offsets within a plane
    uint32_t aoff[2], boff[2];
#pragma unroll
    for (int mat = 0; mat < 2; mat++) {
        const int r = mw + mat * 16 + (lid & 15);
        const int kc = (lid >> 4) * 4;
        aoff[mat] = (uint32_t)(r * 36 + kc) * 4;
    }
#pragma unroll
    for (int p = 0; p < 2; p++) {
        const int r = nw + p * 16 + (lid & 7) + ((lid & 16) >> 1);
        const int kc = ((lid >> 3) & 1) * 4;
        boff[p] = (uint32_t)(r * 36 + kc) * 4;
    }

    float acc[2][4][4];
#pragma unroll
    for (int i = 0; i < 2; i++)
#pragma unroll
        for (int j = 0; j < 4; j++)
#pragma unroll
            for (int q = 0; q < 4; q++) acc[i][j][q] = 0.0f;

    auto fill = [&](int c, uint32_t boffb) {
        const int k0 = c * 64;
#pragma unroll
        for (int i = 0; i < 2; i++) {
            const int idx = tid + i * NTHREADS;
            const int row = idx >> 3, c8 = idx & 7;
            const uint32_t d = sb + boffb + row * SROW_B + c8 * 16;
            const size_t g = (size_t)(m0 + row) * K + k0 + c8 * 8;
            cp16(d, Ahi + g);
            cp16(d + OFF_AL, Alo + g);
        }
#pragma unroll
        for (int i = 0; i < 2; i++) {
            const int idx = tid + i * NTHREADS;
            const int row = idx >> 3, c8 = idx & 7;
            const uint32_t d = sb + boffb + OFF_BH + row * SROW_B + c8 * 16;
            const size_t g = (size_t)(n0 + row) * KH + (k0 >> 1) + c8 * 4;
            cp16(d, Bh + g);
            cp16(d + (OFF_BL - OFF_BH), Bl + g);
        }
    };

    fill(0, 0);
    CP_COMMIT();

    for (int c = 0; c < KCHUNKS; c++) {
        if (c + 1 < KCHUNKS) {
            fill(c + 1, (uint32_t)((c + 1) & 1) * BUF_BYTES);
            CP_COMMIT();
            CP_WAIT1();
        } else {
            CP_WAIT0();
        }
        __syncthreads();

        const uint32_t bufb = sb + (uint32_t)(c & 1) * BUF_BYTES;

#pragma unroll
        for (int ks = 0; ks < 4; ks++) {
            const uint32_t kbB = ks * 32;
            uint32_t ah[2][4], al[2][4], bfh[4][2], bfl[4][2];
#pragma unroll
            for (int mat = 0; mat < 2; mat++) {
                LDSM4(ah[mat][0], ah[mat][1], ah[mat][2], ah[mat][3],
                      bufb + aoff[mat] + kbB);
                LDSM4(al[mat][0], al[mat][1], al[mat][2], al[mat][3],
                      bufb + OFF_AL + aoff[mat] + kbB);
            }
#pragma unroll
            for (int p = 0; p < 2; p++) {
                LDSM4(bfh[2 * p][0], bfh[2 * p][1], bfh[2 * p + 1][0], bfh[2 * p + 1][1],
                      bufb + OFF_BH + boff[p] + kbB);
                LDSM4(bfl[2 * p][0], bfl[2 * p][1], bfl[2 * p + 1][0], bfl[2 * p + 1][1],
                      bufb + OFF_BL + boff[p] + kbB);
            }
#pragma unroll
            for (int mat = 0; mat < 2; mat++)
#pragma unroll
                for (int nat = 0; nat < 4; nat++) {
                    mma16816(acc[mat][nat], ah[mat], bfh[nat]);
                    mma16816(acc[mat][nat], ah[mat], bfl[nat]);
                    mma16816(acc[mat][nat], al[mat], bfh[nat]);
                }
        }
        __syncthreads();
    }

    // ---- epilogue
#pragma unroll
    for (int mat = 0; mat < 2; mat++) {
        const int r0 = m0 + mw + mat * 16 + gid;
#pragma unroll
        for (int nat = 0; nat < 4; nat++) {
            const int n = n0 + nw + nat * 8 + tig * 2;
            float c0 = acc[mat][nat][0], c1 = acc[mat][nat][1];
            float c2 = acc[mat][nat][2], c3 = acc[mat][nat][3];
            if (BIAS) {
                const float bv0 = (n < N) ? bias[n] : 0.0f;
                const float bv1 = (n + 1 < N) ? bias[n + 1] : 0.0f;
                c0 += bv0; c1 += bv1; c2 += bv0; c3 += bv1;
            }
            if (RELU) {
                c0 = fmaxf(c0, 0.0f); c1 = fmaxf(c1, 0.0f);
                c2 = fmaxf(c2, 0.0f); c3 = fmaxf(c3, 0.0f);
            }
            if (FUSE) {
                // concat routing: col<128 -> timestep logits [.,100]; else pattern [.,1000]
                auto route = [&](int row, int col, float v) {
                    if (col < 128) {
                        if (col < NBINS) C[(size_t)row * NBINS + col] = v;
                    } else {
                        const int nc = col - 128;
                        if (nc < NBINS * NPAT) Cpl[(size_t)row * (NBINS * NPAT) + nc] = v;
                    }
                };
                route(r0, n, c0);     route(r0, n + 1, c1);
                route(r0 + 8, n, c2); route(r0 + 8, n + 1, c3);
            } else if (SPLIT_OUT) {
                __nv_bfloat16 h0, l0, h1, l1;
                split2(c0, h0, l0); split2(c1, h1, l1);
                *(uint32_t*)(Chi + (size_t)r0 * N + n) = pack2bf(h0, h1);
                *(uint32_t*)(Clo + (size_t)r0 * N + n) = pack2bf(l0, l1);
                split2(c2, h0, l0); split2(c3, h1, l1);
                *(uint32_t*)(Chi + (size_t)(r0 + 8) * N + n) = pack2bf(h0, h1);
                *(uint32_t*)(Clo + (size_t)(r0 + 8) * N + n) = pack2bf(l0, l1);
            } else {
                *(float2*)(C + (size_t)r0 * N + n) = make_float2(c0, c1);
                *(float2*)(C + (size_t)(r0 + 8) * N + n) = make_float2(c2, c3);
            }
        }
    }
}

// ---------------------------------------------------------------------------
// Prep kernels
// ---------------------------------------------------------------------------
__global__ void k_split(const float* __restrict__ x, __nv_bfloat16* __restrict__ xh,
                        __nv_bfloat16* __restrict__ xl, int n4) {
    const int i = blockIdx.x * blockDim.x + threadIdx.x;
    if (i >= n4) return;
    const float4 v = ((const float4*)x)[i];
    __nv_bfloat16 h0, l0, h1, l1, h2, l2, h3, l3;
    split2(v.x, h0, l0); split2(v.y, h1, l1);
    split2(v.z, h2, l2); split2(v.w, h3, l3);
    ((uint64_t*)xh)[i] = pack4bf(h0, h1, h2, h3);
    ((uint64_t*)xl)[i] = pack4bf(l0, l1, l2, l3);
}

// W [K][N] fp32 -> n-major k-pair packed u32 [Npad][K/2] hi/lo, zero padded
__global__ void k_pack(const float* __restrict__ W, uint32_t* __restrict__ Wh,
                       uint32_t* __restrict__ Wl, int N, int kh, int total) {
    const int idx = blockIdx.x * blockDim.x + threadIdx.x;
    if (idx >= total) return;
    const int n = idx / kh, kp = idx - n * kh;
    float v0 = 0.0f, v1 = 0.0f;
    if (n < N) {
        v0 = W[(size_t)(2 * kp) * N + n];
        v1 = W[(size_t)(2 * kp + 1) * N + n];
    }
    __nv_bfloat16 h0, l0, h1, l1;
    split2(v0, h0, l0); split2(v1, h1, l1);
    Wh[idx] = pack2bf(h0, h1);
    Wl[idx] = pack2bf(l0, l1);
}

// Concat pack: rows 0-127 <- Wt [512,100], rows 128-1151 <- Wp [512,1000]; + bcat
__global__ void k_packcat(const float* __restrict__ Wt, const float* __restrict__ bt,
                          const float* __restrict__ Wp, const float* __restrict__ bp,
                          uint32_t* __restrict__ Wh, uint32_t* __restrict__ Wl,
                          float* __restrict__ bcat) {
    const int kh = SCALE_D / 2;
    const int idx = blockIdx.x * blockDim.x + threadIdx.x;
    if (idx >= NCAT * kh) return;
    const int r = idx / kh, kp = idx - r * kh;
    const float* W; int n, N;
    if (r < 128) { W = Wt; n = r; N = NBINS; }
    else         { W = Wp; n = r - 128; N = NBINS * NPAT; }
    float v0 = 0.0f, v1 = 0.0f;
    if (n < N) {
        v0 = W[(size_t)(2 * kp) * N + n];
        v1 = W[(size_t)(2 * kp + 1) * N + n];
    }
    __nv_bfloat16 h0, l0, h1, l1;
    split2(v0, h0, l0); split2(v1, h1, l1);
    Wh[idx] = pack2bf(h0, h1);
    Wl[idx] = pack2bf(l0, l1);
    if (kp == 0)
        bcat[r] = (r < 128) ? ((n < NBINS) ? bt[n] : 0.0f)
                            : ((n < NBINS * NPAT) ? bp[n] : 0.0f);
}

// ---------------------------------------------------------------------------
// Exact timestep class + max reduction
// ---------------------------------------------------------------------------
__device__ __forceinline__ int ts_class(int ts) {
    int c = ts / 10;
    return min(max(c, 0), NBINS - 1);
}
__global__ void k_maxclass(const int* __restrict__ ts, int n) {
    int i = blockIdx.x * blockDim.x + threadIdx.x;
    int local = 0;
    for (; i < n; i += gridDim.x * blockDim.x)
        local = max(local, ts_class(ts[i]));
#pragma unroll
    for (int o = 16; o; o >>= 1)
        local = max(local, __shfl_xor_sync(0xffffffffu, local, o));
    if ((threadIdx.x & 31) == 0) atomicMax(&g_maxclass, local);
}

// ---------------------------------------------------------------------------
// Row normalize: one WARP per row; all fp32 (no fp64 on the hot path).
// ---------------------------------------------------------------------------
__global__ __launch_bounds__(256)
void k_norm(const float* __restrict__ zraw,
            const float* __restrict__ w_pos,
            float* __restrict__ out_z,
            __nv_bfloat16* __restrict__ zh,
            __nv_bfloat16* __restrict__ zl,
            float* __restrict__ out_dot) {
    const int lid = threadIdx.x & 31;
    const int row = blockIdx.x * 8 + (threadIdx.x >> 5);

    const float4* zr = (const float4*)(zraw + (size_t)row * SCALE_D);
    const float4* wp = (const float4*)w_pos;

    float4 zv[4];
    float ss = 0.0f;
#pragma unroll
    for (int i = 0; i < 4; i++) {
        zv[i] = zr[lid + 32 * i];
        ss += zv[i].x * zv[i].x + zv[i].y * zv[i].y +
              zv[i].z * zv[i].z + zv[i].w * zv[i].w;
    }
#pragma unroll
    for (int o = 16; o; o >>= 1)
        ss += __shfl_xor_sync(0xffffffffu, ss, o);

    const float nrm = fmaxf(__fsqrt_rn(ss), 1e-12f);

    float4* zo = (float4*)(out_z + (size_t)row * SCALE_D);
    float dd = 0.0f;
#pragma unroll
    for (int i = 0; i < 4; i++) {
        float4 o;
        const float4 wv = wp[lid + 32 * i];
        o.x = __fdiv_rn(zv[i].x, nrm);
        o.y = __fdiv_rn(zv[i].y, nrm);
        o.z = __fdiv_rn(zv[i].z, nrm);
        o.w = __fdiv_rn(zv[i].w, nrm);
        zo[lid + 32 * i] = o;
        __nv_bfloat16 h0, l0, h1, l1, h2, l2, h3, l3;
        split2(o.x, h0, l0); split2(o.y, h1, l1);
        split2(o.z, h2, l2); split2(o.w, h3, l3);
        const size_t e = (size_t)row * SCALE_D + (lid + 32 * i) * 4;
        *(uint64_t*)(zh + e) = pack4bf(h0, h1, h2, h3);
        *(uint64_t*)(zl + e) = pack4bf(l0, l1, l2, l3);
        dd += o.x * wv.x + o.y * wv.y + o.z * wv.z + o.w * wv.w;
    }
#pragma unroll
    for (int o = 16; o; o >>= 1)
        dd += __shfl_xor_sync(0xffffffffu, dd, o);

    if (lid == 0) out_dot[row] = dd;
}

// ---------------------------------------------------------------------------
// Cantor staircase: one THREAD per row. Core recurrence identical since R4.
// ---------------------------------------------------------------------------
__global__ __launch_bounds__(256)
void k_cantor(const float* __restrict__ dot,
              const float* __restrict__ b_pos,
              const float* __restrict__ alpha_p,
              const int* __restrict__ timesteps,
              float* __restrict__ out_tc,
              float* __restrict__ out_cv) {
    const int row = blockIdx.x * blockDim.x + threadIdx.x;
    if (row >= BATCH) return;

    const float tot_dd = dot[row];
    const int cls = ts_class(timesteps[row]);

    const int max_pos = g_maxclass + 1;
    const float denom = (float)max(max_pos - 1, 1);
    const float pos_f = (float)cls;
    float x = (max_pos > 1) ? __fdiv_rn(pos_f, denom) : pos_f;
    x = fminf(fmaxf(x, XMINF), XMAXF);

    const float pre = __fadd_rn(tot_dd, b_pos[0]);
    const float shift = __fmul_rn((float)tanh((double)pre), 0.3f);
    x = fminf(fmaxf(__fadd_rn(x, shift), XMINF), XMAXF);

    const double alpha = (double)(*alpha_p);
    const float tau_d = __fadd_rn(0.25f, 1e-8f);
    double Cx = 0.0;
    double w = 0.5;
#pragma unroll
    for (int L = 0; L < 12; L++) {
        const float y = __fmul_rn(x, 3.0f);
        const float d0 = __fadd_rn(y, -0.5f);
        const float d1 = __fadd_rn(y, -1.5f);
        const float d2 = __fadd_rn(y, -2.5f);
        const float l0 = __fdiv_rn(-__fmul_rn(d0, d0), tau_d);
        const float l1 = __fdiv_rn(-__fmul_rn(d1, d1), tau_d);
        const float l2 = __fdiv_rn(-__fmul_rn(d2, d2), tau_d);
        const float m = fmaxf(l0, fmaxf(l1, l2));
        const double e0 = exp((double)__fadd_rn(l0, -m));
        const double e1 = exp((double)__fadd_rn(l1, -m));
        const double e2 = exp((double)__fadd_rn(l2, -m));
        const double inv_s = 1.0 / (e0 + e1 + e2);
        const double bit = e1 * inv_s * alpha + e2 * inv_s;
        Cx += bit * w;
        w *= 0.5;
        x = __fadd_rn(y, -floorf(y));
    }
    out_tc[row] = (float)cls;
    float cvf = (float)Cx;
    out_cv[row] = fminf(fmaxf(cvf, 0.0f), 1.0f);
}

// ---------------------------------------------------------------------------
// Launch  (GEMM1 is the 6th launch -> ncu -s 5 -c 1 profiles it)
// ---------------------------------------------------------------------------
extern "C" void kernel_launch(void* const* d_in, const int* in_sizes, int n_in,
                              void* d_out, int out_size) {
    const float* features = (const float*)d_in[0];
    const int*   timesteps = (const int*)d_in[1];
    const float* W1    = (const float*)d_in[2];
    const float* b1    = (const float*)d_in[3];
    const float* W2    = (const float*)d_in[4];
    const float* Wt    = (const float*)d_in[5];
    const float* bt    = (const float*)d_in[6];
    const float* Wp    = (const float*)d_in[7];
    const float* bp    = (const float*)d_in[8];
    const float* w_pos = (const float*)d_in[9];
    const float* b_pos = (const float*)d_in[10];
    const float* alpha = (const float*)d_in[11];

    float* out = (float*)d_out;
    float* out_z  = out + Z_OFF;
    float* out_tl = out + TL_OFF;
    float* out_pl = out + PL_OFF;
    float* out_tc = out + TC_OFF;
    float* out_cv = out + CV_OFF;

    __nv_bfloat16 *fh, *fl, *hh, *hl, *zh, *zl;
    uint32_t *w1h, *w1l, *w2h, *w2l, *wch, *wcl;
    float *zraw, *dot, *bcat; void* maxp;
    cudaGetSymbolAddress((void**)&fh, g_fh);   cudaGetSymbolAddress((void**)&fl, g_fl);
    cudaGetSymbolAddress((void**)&hh, g_hh);   cudaGetSymbolAddress((void**)&hl, g_hl);
    cudaGetSymbolAddress((void**)&zh, g_zh);   cudaGetSymbolAddress((void**)&zl, g_zl);
    cudaGetSymbolAddress((void**)&w1h, g_w1h); cudaGetSymbolAddress((void**)&w1l, g_w1l);
    cudaGetSymbolAddress((void**)&w2h, g_w2h); cudaGetSymbolAddress((void**)&w2l, g_w2l);
    cudaGetSymbolAddress((void**)&wch, g_wch); cudaGetSymbolAddress((void**)&wcl, g_wcl);
    cudaGetSymbolAddress((void**)&bcat, g_bcat);
    cudaGetSymbolAddress((void**)&zraw, g_zraw);
    cudaGetSymbolAddress((void**)&dot, g_dot);
    cudaGetSymbolAddress(&maxp, g_maxclass);

    auto* g1  = tc_gemm<IN_DIM / 64, true, true, true, false>;
    auto* g2  = tc_gemm<BELLY / 64, false, false, false, false>;
    auto* g34 = tc_gemm<SCALE_D / 64, true, false, false, true>;
    cudaFuncSetAttribute(g1,  cudaFuncAttributeMaxDynamicSharedMemorySize, SM_TOTAL);
    cudaFuncSetAttribute(g2,  cudaFuncAttributeMaxDynamicSharedMemorySize, SM_TOTAL);
    cudaFuncSetAttribute(g34, cudaFuncAttributeMaxDynamicSharedMemorySize, SM_TOTAL);

    cudaMemsetAsync(maxp, 0, sizeof(int), 0);          // 1
    k_maxclass<<<32, 256>>>(timesteps, BATCH);         // 2

    const int n4 = BATCH * IN_DIM / 4;
    k_split<<<(n4 + 255) / 256, 256>>>(features, fh, fl, n4);                 // 3
    const int t1 = 1024 * (IN_DIM / 2);
    k_pack<<<(t1 + 255) / 256, 256>>>(W1, w1h, w1l, BELLY, IN_DIM / 2, t1);   // 4
    const int t2 = 512 * (BELLY / 2);
    k_pack<<<(t2 + 255) / 256, 256>>>(W2, w2h, w2l, SCALE_D, BELLY / 2, t2);  // 5

    // GEMM1 (6th launch, profiled): h(split) = relu(features @ W1 + b1)
    g1<<<dim3(BELLY / 128, BATCH / 128), NTHREADS, SM_TOTAL>>>(
        fh, fl, w1h, w1l, b1, nullptr, nullptr, hh, hl, BELLY);

    // GEMM2: zraw = h @ W2
    g2<<<dim3(SCALE_D / 128, BATCH / 128), NTHREADS, SM_TOTAL>>>(
        hh, hl, w2h, w2l, nullptr, zraw, nullptr, nullptr, nullptr, SCALE_D);

    k_norm<<<BATCH / 8, 256>>>(zraw, w_pos, out_z, zh, zl, dot);
    k_cantor<<<(BATCH + 255) / 256, 256>>>(dot, b_pos, alpha, timesteps, out_tc, out_cv);

    const int tc = NCAT * (SCALE_D / 2);
    k_packcat<<<(tc + 255) / 256, 256>>>(Wt, bt, Wp, bp, wch, wcl, bcat);

    // Fused GEMM3+GEMM4: [timestep_logits | pattern_logits] = z @ [Wt|Wp] + [bt|bp]
    g34<<<dim3(NCAT / 128, BATCH / 128), NTHREADS, SM_TOTAL>>>(
        zh, zl, wch, wcl, bcat, out_tl, out_pl, nullptr, nullptr, NCAT);
}